// round 5
// baseline (speedup 1.0000x reference)
#include <cuda_runtime.h>
#include <cuda_bf16.h>
#include <cstdint>
#include <math.h>

#define B_  4
#define S_  2048
#define H_  16
#define DK_ 64
#define D_  1024

// Scratch (device globals — allocation-free rule)
__device__ float g_q [B_*H_*S_*DK_];
__device__ float g_k [B_*H_*S_*DK_];
__device__ float g_v [B_*H_*S_*DK_];
__device__ float g_ao[B_*S_*D_];

// ======================= helpers ===========================================
__device__ __forceinline__ void mma_bf16(float* c,
                                         uint32_t a0, uint32_t a1, uint32_t a2, uint32_t a3,
                                         uint32_t b0, uint32_t b1) {
    asm volatile(
        "mma.sync.aligned.m16n8k16.row.col.f32.bf16.bf16.f32 "
        "{%0,%1,%2,%3}, {%4,%5,%6,%7}, {%8,%9}, {%0,%1,%2,%3};"
        : "+f"(c[0]), "+f"(c[1]), "+f"(c[2]), "+f"(c[3])
        : "r"(a0), "r"(a1), "r"(a2), "r"(a3), "r"(b0), "r"(b1));
}

// split a float pair into packed bf16x2 hi and lo (lo = x - hi, rounded)
__device__ __forceinline__ void cvt_hilo(float x, float y, uint32_t& hi, uint32_t& lo) {
    __nv_bfloat162 h = __floats2bfloat162_rn(x, y);
    float hx = __bfloat162float(h.x);
    float hy = __bfloat162float(h.y);
    __nv_bfloat162 l = __floats2bfloat162_rn(x - hx, y - hy);
    hi = *(uint32_t*)&h;
    lo = *(uint32_t*)&l;
}

// ---------------------------------------------------------------------------
// bf16x3 NT GEMM: C[M,N] = A[M,1024] * W[N,1024]^T, CTA 128x128, BK=32 fp32,
// 256 thr (8 warps 4Mx2N), warp tile 32x64.
// ---------------------------------------------------------------------------
#define PST 20   // pairs per smem row (16 data + 4 pad) => conflict-free frags
#define MM_SMEM_BYTES (4 * 128 * PST * 4)   // 40960

template<int MODE>
__global__ void __launch_bounds__(256) mm_bf16x3(const float* __restrict__ A,
                                                 const float* __restrict__ W,
                                                 float* __restrict__ C) {
    extern __shared__ uint32_t smu[];
    uint32_t* Ahs = smu;
    uint32_t* Als = smu + 128*PST;
    uint32_t* Whs = smu + 2*128*PST;
    uint32_t* Wls = smu + 3*128*PST;

    const int tid = threadIdx.x;
    const int w   = tid >> 5;
    const int l   = tid & 31;
    const int wm  = w & 3;
    const int wn  = w >> 2;
    const int g   = l >> 2;
    const int tq  = l & 3;
    const int bm = blockIdx.y, bn = blockIdx.x;
    if (MODE == 1) A = g_ao;

    const float* Ag = A + (size_t)bm * 128 * 1024;
    const float* Wg = W + (size_t)bn * 128 * 1024;

    const int grow = tid >> 1;
    const int gq   = (tid & 1) * 4;

    float4 sa[4], sw[4];
    auto ldg_chunk = [&](int c) {
#pragma unroll
        for (int q = 0; q < 4; q++) {
            sa[q] = *(const float4*)(Ag + (size_t)grow * 1024 + c * 32 + (gq + q) * 4);
            sw[q] = *(const float4*)(Wg + (size_t)grow * 1024 + c * 32 + (gq + q) * 4);
        }
    };
    auto sts_chunk = [&]() {
#pragma unroll
        for (int q = 0; q < 4; q++) {
            int pb = grow * PST + 2 * (gq + q);
            uint32_t h0, l0, h1, l1;
            cvt_hilo(sa[q].x, sa[q].y, h0, l0);
            cvt_hilo(sa[q].z, sa[q].w, h1, l1);
            Ahs[pb] = h0; Ahs[pb + 1] = h1;
            Als[pb] = l0; Als[pb + 1] = l1;
            cvt_hilo(sw[q].x, sw[q].y, h0, l0);
            cvt_hilo(sw[q].z, sw[q].w, h1, l1);
            Whs[pb] = h0; Whs[pb + 1] = h1;
            Wls[pb] = l0; Wls[pb + 1] = l1;
        }
    };

    float acc[2][8][4];
#pragma unroll
    for (int mi = 0; mi < 2; mi++)
#pragma unroll
        for (int ni = 0; ni < 8; ni++)
#pragma unroll
            for (int r = 0; r < 4; r++) acc[mi][ni][r] = 0.f;

    const int row0 = wm * 32;
    const int col0 = wn * 64;

    ldg_chunk(0);
    sts_chunk();
    __syncthreads();

    for (int c = 0; c < 32; c++) {
        if (c + 1 < 32) ldg_chunk(c + 1);

#pragma unroll
        for (int ks = 0; ks < 2; ks++) {
            const int kc = ks * 8;
            uint32_t ah[2][4], al[2][4];
#pragma unroll
            for (int mi = 0; mi < 2; mi++) {
                int ra = (row0 + mi * 16 + g) * PST + kc + tq;
                int rb = ra + 8 * PST;
                ah[mi][0] = Ahs[ra];     ah[mi][1] = Ahs[rb];
                ah[mi][2] = Ahs[ra + 4]; ah[mi][3] = Ahs[rb + 4];
                al[mi][0] = Als[ra];     al[mi][1] = Als[rb];
                al[mi][2] = Als[ra + 4]; al[mi][3] = Als[rb + 4];
            }
#pragma unroll
            for (int ni = 0; ni < 8; ni++) {
                int rn = (col0 + ni * 8 + g) * PST + kc + tq;
                uint32_t bh0 = Whs[rn], bh1 = Whs[rn + 4];
                uint32_t bl0 = Wls[rn], bl1 = Wls[rn + 4];
#pragma unroll
                for (int mi = 0; mi < 2; mi++) {
                    mma_bf16(acc[mi][ni], ah[mi][0], ah[mi][1], ah[mi][2], ah[mi][3], bh0, bh1);
                    mma_bf16(acc[mi][ni], ah[mi][0], ah[mi][1], ah[mi][2], ah[mi][3], bl0, bl1);
                    mma_bf16(acc[mi][ni], al[mi][0], al[mi][1], al[mi][2], al[mi][3], bh0, bh1);
                }
            }
        }
        __syncthreads();
        if (c + 1 < 32) {
            sts_chunk();
            __syncthreads();
        }
    }

#pragma unroll
    for (int mi = 0; mi < 2; mi++) {
#pragma unroll
        for (int half = 0; half < 2; half++) {
            int r = bm * 128 + row0 + mi * 16 + g + half * 8;
#pragma unroll
            for (int ni = 0; ni < 8; ni++) {
                int cb = bn * 128 + col0 + ni * 8 + 2 * tq;
                float2 val = make_float2(acc[mi][ni][half * 2 + 0],
                                         acc[mi][ni][half * 2 + 1]);
                if (MODE == 0) {
                    int which = cb >> 10;
                    int h  = (cb >> 6) & 15;
                    int d0 = cb & 63;
                    int b  = r >> 11;
                    int s  = r & 2047;
                    float* dst = (which == 0) ? g_q : (which == 1) ? g_k : g_v;
                    *(float2*)(dst + (((size_t)(b * H_ + h) * S_ + s) * DK_ + d0)) = val;
                } else {
                    *(float2*)(C + (size_t)r * D_ + cb) = val;
                }
            }
        }
    }
}

// ---------------------------------------------------------------------------
// RoPE in-place on g_q and g_k.
// ---------------------------------------------------------------------------
__global__ void rope_kernel() {
    const int NP = B_*H_*S_*32;
    int idx = blockIdx.x * blockDim.x + threadIdx.x;
    if (idx >= 2 * NP) return;
    int t   = (idx >= NP) ? 1 : 0;
    int i   = idx - t * NP;
    int pr  = i & 31;
    int row = i >> 5;
    int s   = row & (S_ - 1);
    float invf = exp2f(-(float)pr * (13.28771237954945f / 32.0f));
    float ang = (float)s * invf;
    float sn, cs;
    sincosf(ang, &sn, &cs);
    float* base = (t ? g_k : g_q) + (size_t)row * DK_ + pr * 2;
    float x1 = base[0], x2 = base[1];
    base[0] = x1 * cs - x2 * sn;
    base[1] = x1 * sn + x2 * cs;
}

// ---------------------------------------------------------------------------
// Flash attention, bf16x3 tensor-core version.
// BQ=BK=64, 128 thr (4 warps x 16 q-rows), causal + softcap, online softmax.
// smem: Q/K hi,lo [64 rows][36 pairs(dk)]; V hi,lo transposed [64 dk][36 pairs(kv)]
// P stays in registers (C-frag of S == A-frag of PV).
// ---------------------------------------------------------------------------
#define FST 36
#define FLASH_SMEM_BYTES (6 * 64 * FST * 4)   // 55296

__global__ void __launch_bounds__(128) flash_mma() {
    extern __shared__ uint32_t su[];
    uint32_t* Qh = su;
    uint32_t* Ql = Qh + 64*FST;
    uint32_t* Kh = Ql + 64*FST;
    uint32_t* Kl = Kh + 64*FST;
    uint32_t* Vh = Kl + 64*FST;   // [dk col][kv pair]
    uint32_t* Vl = Vh + 64*FST;

    const int tid = threadIdx.x;
    const int w = tid >> 5, l = tid & 31;
    const int g = l >> 2, tq = l & 3;
    const int q0 = blockIdx.x * 64;
    const int h = blockIdx.y, b = blockIdx.z;
    const size_t bh = (size_t)(b*H_ + h) * S_ * DK_;
    const float* Qg = g_q + bh + (size_t)q0 * DK_;
    const float* Kg = g_k + bh;
    const float* Vg = g_v + bh;

    // ---- Q tile -> smem hi/lo pairs ----
    {
        int row = tid >> 1, pb = (tid & 1) * 16;
        const float* src = Qg + row * DK_ + pb * 2;
#pragma unroll
        for (int q = 0; q < 8; q++) {
            float4 v = *(const float4*)(src + q * 4);
            uint32_t h0, l0, h1, l1;
            cvt_hilo(v.x, v.y, h0, l0);
            cvt_hilo(v.z, v.w, h1, l1);
            int pp = row * FST + pb + q * 2;
            Qh[pp] = h0; Qh[pp + 1] = h1;
            Ql[pp] = l0; Ql[pp + 1] = l1;
        }
    }
    __syncthreads();

    // hoist Q fragments for this warp's 16 rows
    uint32_t qh[4][4], ql[4][4];
#pragma unroll
    for (int kk = 0; kk < 4; kk++) {
        int ra = (w * 16 + g) * FST + kk * 8 + tq;
        int rb = ra + 8 * FST;
        qh[kk][0] = Qh[ra];     qh[kk][1] = Qh[rb];
        qh[kk][2] = Qh[ra + 4]; qh[kk][3] = Qh[rb + 4];
        ql[kk][0] = Ql[ra];     ql[kk][1] = Ql[rb];
        ql[kk][2] = Ql[ra + 4]; ql[kk][3] = Ql[rb + 4];
    }

    float m0 = -INFINITY, m1 = -INFINITY, l0s = 0.f, l1s = 0.f;
    float o[8][4];
#pragma unroll
    for (int ni = 0; ni < 8; ni++)
#pragma unroll
        for (int r = 0; r < 4; r++) o[ni][r] = 0.f;

    const int ig0 = q0 + w * 16 + g;
    const int ig1 = ig0 + 8;
    const int nkt = q0 >> 6;

    for (int kt = 0; kt <= nkt; kt++) {
        __syncthreads();   // protect K/V smem from previous-iter readers
        // K tile -> smem hi/lo pairs (row-major along dk)
        {
            int row = tid >> 1, pb = (tid & 1) * 16;
            const float* src = Kg + (size_t)(kt * 64 + row) * DK_ + pb * 2;
#pragma unroll
            for (int q = 0; q < 8; q++) {
                float4 v = *(const float4*)(src + q * 4);
                uint32_t h0, l0, h1, l1;
                cvt_hilo(v.x, v.y, h0, l0);
                cvt_hilo(v.z, v.w, h1, l1);
                int pp = row * FST + pb + q * 2;
                Kh[pp] = h0; Kh[pp + 1] = h1;
                Kl[pp] = l0; Kl[pp + 1] = l1;
            }
        }
        // V tile -> smem transposed-packed (pairs along kv)
        {
            int p = tid & 31;                 // kv pair index
#pragma unroll
            for (int cg = (tid >> 5); cg < 16; cg += 4) {
                int c = cg * 4;
                const float* r0 = Vg + (size_t)(kt * 64 + 2 * p) * DK_ + c;
                float4 va = *(const float4*)r0;
                float4 vb = *(const float4*)(r0 + DK_);
                uint32_t hh, ll;
                cvt_hilo(va.x, vb.x, hh, ll); Vh[(c+0)*FST + p] = hh; Vl[(c+0)*FST + p] = ll;
                cvt_hilo(va.y, vb.y, hh, ll); Vh[(c+1)*FST + p] = hh; Vl[(c+1)*FST + p] = ll;
                cvt_hilo(va.z, vb.z, hh, ll); Vh[(c+2)*FST + p] = hh; Vl[(c+2)*FST + p] = ll;
                cvt_hilo(va.w, vb.w, hh, ll); Vh[(c+3)*FST + p] = hh; Vl[(c+3)*FST + p] = ll;
            }
        }
        __syncthreads();

        // S = Q K^T (bf16x3)
        float sc[8][4];
#pragma unroll
        for (int ni = 0; ni < 8; ni++)
#pragma unroll
            for (int r = 0; r < 4; r++) sc[ni][r] = 0.f;
#pragma unroll
        for (int kk = 0; kk < 4; kk++) {
#pragma unroll
            for (int ni = 0; ni < 8; ni++) {
                int rn = (ni * 8 + g) * FST + kk * 8 + tq;
                uint32_t bh0 = Kh[rn], bh1 = Kh[rn + 4];
                uint32_t bl0 = Kl[rn], bl1 = Kl[rn + 4];
                mma_bf16(sc[ni], qh[kk][0], qh[kk][1], qh[kk][2], qh[kk][3], bh0, bh1);
                mma_bf16(sc[ni], qh[kk][0], qh[kk][1], qh[kk][2], qh[kk][3], bl0, bl1);
                mma_bf16(sc[ni], ql[kk][0], ql[kk][1], ql[kk][2], ql[kk][3], bh0, bh1);
            }
        }

        // scale + softcap + causal mask
        const bool diag = (kt == nkt);
#pragma unroll
        for (int ni = 0; ni < 8; ni++) {
            int jg = kt * 64 + ni * 8 + 2 * tq;
#pragma unroll
            for (int r = 0; r < 4; r++) {
                float v = sc[ni][r] * 0.125f;
                v = 50.0f * tanhf(v * 0.02f);
                if (diag) {
                    int col = jg + (r & 1);
                    int row = (r < 2) ? ig0 : ig1;
                    if (col > row) v = -1e30f;
                }
                sc[ni][r] = v;
            }
        }

        // online softmax (rows g and g+8; reduce over tq lanes)
        float mx0 = -INFINITY, mx1 = -INFINITY;
#pragma unroll
        for (int ni = 0; ni < 8; ni++) {
            mx0 = fmaxf(mx0, fmaxf(sc[ni][0], sc[ni][1]));
            mx1 = fmaxf(mx1, fmaxf(sc[ni][2], sc[ni][3]));
        }
        mx0 = fmaxf(mx0, __shfl_xor_sync(0xffffffffu, mx0, 1));
        mx0 = fmaxf(mx0, __shfl_xor_sync(0xffffffffu, mx0, 2));
        mx1 = fmaxf(mx1, __shfl_xor_sync(0xffffffffu, mx1, 1));
        mx1 = fmaxf(mx1, __shfl_xor_sync(0xffffffffu, mx1, 2));
        float mn0 = fmaxf(m0, mx0), mn1 = fmaxf(m1, mx1);
        float s0 = 0.f, s1 = 0.f;
#pragma unroll
        for (int ni = 0; ni < 8; ni++) {
            sc[ni][0] = __expf(sc[ni][0] - mn0);
            sc[ni][1] = __expf(sc[ni][1] - mn0);
            sc[ni][2] = __expf(sc[ni][2] - mn1);
            sc[ni][3] = __expf(sc[ni][3] - mn1);
            s0 += sc[ni][0] + sc[ni][1];
            s1 += sc[ni][2] + sc[ni][3];
        }
        s0 += __shfl_xor_sync(0xffffffffu, s0, 1);
        s0 += __shfl_xor_sync(0xffffffffu, s0, 2);
        s1 += __shfl_xor_sync(0xffffffffu, s1, 1);
        s1 += __shfl_xor_sync(0xffffffffu, s1, 2);
        float c0 = __expf(m0 - mn0), c1 = __expf(m1 - mn1);
        l0s = l0s * c0 + s0; l1s = l1s * c1 + s1;
        m0 = mn0; m1 = mn1;
#pragma unroll
        for (int ni = 0; ni < 8; ni++) {
            o[ni][0] *= c0; o[ni][1] *= c0;
            o[ni][2] *= c1; o[ni][3] *= c1;
        }

        // pack P into A-fragments (hi/lo)
        uint32_t ph[4][4], pl[4][4];
#pragma unroll
        for (int kk = 0; kk < 4; kk++) {
            int n0 = 2 * kk, n1 = 2 * kk + 1;
            cvt_hilo(sc[n0][0], sc[n0][1], ph[kk][0], pl[kk][0]);
            cvt_hilo(sc[n0][2], sc[n0][3], ph[kk][1], pl[kk][1]);
            cvt_hilo(sc[n1][0], sc[n1][1], ph[kk][2], pl[kk][2]);
            cvt_hilo(sc[n1][2], sc[n1][3], ph[kk][3], pl[kk][3]);
        }

        // O += P V (bf16x3)
#pragma unroll
        for (int kk = 0; kk < 4; kk++) {
#pragma unroll
            for (int ni = 0; ni < 8; ni++) {
                int rn = (ni * 8 + g) * FST + kk * 8 + tq;
                uint32_t bh0 = Vh[rn], bh1 = Vh[rn + 4];
                uint32_t bl0 = Vl[rn], bl1 = Vl[rn + 4];
                mma_bf16(o[ni], ph[kk][0], ph[kk][1], ph[kk][2], ph[kk][3], bh0, bh1);
                mma_bf16(o[ni], ph[kk][0], ph[kk][1], ph[kk][2], ph[kk][3], bl0, bl1);
                mma_bf16(o[ni], pl[kk][0], pl[kk][1], pl[kk][2], pl[kk][3], bh0, bh1);
            }
        }
    }

    // epilogue: normalize, write [b,s,h,dk]
    float inv0 = 1.0f / l0s, inv1 = 1.0f / l1s;
    float* d0 = g_ao + ((size_t)(b * S_ + ig0) * H_ + h) * DK_;
    float* d1 = g_ao + ((size_t)(b * S_ + ig1) * H_ + h) * DK_;
#pragma unroll
    for (int ni = 0; ni < 8; ni++) {
        int col = ni * 8 + 2 * tq;
        *(float2*)(d0 + col) = make_float2(o[ni][0] * inv0, o[ni][1] * inv0);
        *(float2*)(d1 + col) = make_float2(o[ni][2] * inv1, o[ni][3] * inv1);
    }
}

// ---------------------------------------------------------------------------
extern "C" void kernel_launch(void* const* d_in, const int* in_sizes, int n_in,
                              void* d_out, int out_size) {
    const float* x     = (const float*)d_in[0];   // [4,2048,1024]
    const float* w_qkv = (const float*)d_in[1];   // [3072,1024]
    const float* w_out = (const float*)d_in[2];   // [1024,1024]
    float* out = (float*)d_out;                   // [4,2048,1024]

    cudaFuncSetAttribute(mm_bf16x3<0>, cudaFuncAttributeMaxDynamicSharedMemorySize, MM_SMEM_BYTES);
    cudaFuncSetAttribute(mm_bf16x3<1>, cudaFuncAttributeMaxDynamicSharedMemorySize, MM_SMEM_BYTES);
    cudaFuncSetAttribute(flash_mma,    cudaFuncAttributeMaxDynamicSharedMemorySize, FLASH_SMEM_BYTES);

    // 1) QKV projection (bf16x3 mma.sync) with scatter into per-head layout
    mm_bf16x3<0><<<dim3(24, 64), 256, MM_SMEM_BYTES>>>(x, w_qkv, nullptr);

    // 2) RoPE on q, k
    rope_kernel<<<32768, 256>>>();

    // 3) Flash attention (bf16x3 mma.sync)
    flash_mma<<<dim3(S_/64, H_, B_), 128, FLASH_SMEM_BYTES>>>();

    // 4) Output projection (bf16x3 mma.sync)
    mm_bf16x3<1><<<dim3(8, 64), 256, MM_SMEM_BYTES>>>(nullptr, w_out, out);
}

// round 7
// speedup vs baseline: 1.6530x; 1.6530x over previous
#include <cuda_runtime.h>
#include <cuda_bf16.h>
#include <cstdint>
#include <math.h>

#define B_  4
#define S_  2048
#define H_  16
#define DK_ 64
#define D_  1024

// Scratch (device globals — allocation-free rule)
__device__ float    g_v [B_*H_*S_*DK_];          // V fp32 [b,h,s,dk]
__device__ float    g_ao[B_*S_*D_];
__device__ uint32_t g_qh[B_*H_*S_*32];           // packed bf16x2 pairs [b,h,s,32]
__device__ uint32_t g_ql[B_*H_*S_*32];
__device__ uint32_t g_kh[B_*H_*S_*32];
__device__ uint32_t g_kl[B_*H_*S_*32];
__device__ uint32_t g_vh[B_*H_*DK_*(S_/2)];      // packed pairs along s: [b,h][dk][1024]
__device__ uint32_t g_vl[B_*H_*DK_*(S_/2)];

// ======================= helpers ===========================================
__device__ __forceinline__ void mma_bf16(float* c,
                                         uint32_t a0, uint32_t a1, uint32_t a2, uint32_t a3,
                                         uint32_t b0, uint32_t b1) {
    asm volatile(
        "mma.sync.aligned.m16n8k16.row.col.f32.bf16.bf16.f32 "
        "{%0,%1,%2,%3}, {%4,%5,%6,%7}, {%8,%9}, {%0,%1,%2,%3};"
        : "+f"(c[0]), "+f"(c[1]), "+f"(c[2]), "+f"(c[3])
        : "r"(a0), "r"(a1), "r"(a2), "r"(a3), "r"(b0), "r"(b1));
}

__device__ __forceinline__ void cvt_hilo(float x, float y, uint32_t& hi, uint32_t& lo) {
    __nv_bfloat162 h = __floats2bfloat162_rn(x, y);
    float hx = __bfloat162float(h.x);
    float hy = __bfloat162float(h.y);
    __nv_bfloat162 l = __floats2bfloat162_rn(x - hx, y - hy);
    hi = *(uint32_t*)&h;
    lo = *(uint32_t*)&l;
}

// ---------------------------------------------------------------------------
// bf16x3 NT GEMM: C[M,N] = A[M,1024] * W[N,1024]^T, CTA 128x128, BK=32 fp32,
// 256 thr (8 warps 4Mx2N), warp tile 32x64.
// MODE 0: A = x; epilogue applies RoPE to q/k pairs, splits hi/lo bf16, writes
//         g_qh/g_ql/g_kh/g_kl packed; V written fp32 to g_v.
// MODE 1: A = g_ao; plain fp32 store to C.
// ---------------------------------------------------------------------------
#define PST 20
#define MM_SMEM_BYTES (4 * 128 * PST * 4)   // 40960

template<int MODE>
__global__ void __launch_bounds__(256) mm_bf16x3(const float* __restrict__ A,
                                                 const float* __restrict__ W,
                                                 float* __restrict__ C) {
    extern __shared__ uint32_t smu[];
    uint32_t* Ahs = smu;
    uint32_t* Als = smu + 128*PST;
    uint32_t* Whs = smu + 2*128*PST;
    uint32_t* Wls = smu + 3*128*PST;

    const int tid = threadIdx.x;
    const int w   = tid >> 5;
    const int l   = tid & 31;
    const int wm  = w & 3;
    const int wn  = w >> 2;
    const int g   = l >> 2;
    const int tq  = l & 3;
    const int bm = blockIdx.y, bn = blockIdx.x;
    if (MODE == 1) A = g_ao;

    const float* Ag = A + (size_t)bm * 128 * 1024;
    const float* Wg = W + (size_t)bn * 128 * 1024;

    const int grow = tid >> 1;
    const int gq   = (tid & 1) * 4;

    float4 sa[4], sw[4];
    auto ldg_chunk = [&](int c) {
#pragma unroll
        for (int q = 0; q < 4; q++) {
            sa[q] = *(const float4*)(Ag + (size_t)grow * 1024 + c * 32 + (gq + q) * 4);
            sw[q] = *(const float4*)(Wg + (size_t)grow * 1024 + c * 32 + (gq + q) * 4);
        }
    };
    auto sts_chunk = [&]() {
#pragma unroll
        for (int q = 0; q < 4; q++) {
            int pb = grow * PST + 2 * (gq + q);
            uint32_t h0, l0, h1, l1;
            cvt_hilo(sa[q].x, sa[q].y, h0, l0);
            cvt_hilo(sa[q].z, sa[q].w, h1, l1);
            Ahs[pb] = h0; Ahs[pb + 1] = h1;
            Als[pb] = l0; Als[pb + 1] = l1;
            cvt_hilo(sw[q].x, sw[q].y, h0, l0);
            cvt_hilo(sw[q].z, sw[q].w, h1, l1);
            Whs[pb] = h0; Whs[pb + 1] = h1;
            Wls[pb] = l0; Wls[pb + 1] = l1;
        }
    };

    float acc[2][8][4];
#pragma unroll
    for (int mi = 0; mi < 2; mi++)
#pragma unroll
        for (int ni = 0; ni < 8; ni++)
#pragma unroll
            for (int r = 0; r < 4; r++) acc[mi][ni][r] = 0.f;

    const int row0 = wm * 32;
    const int col0 = wn * 64;

    ldg_chunk(0);
    sts_chunk();
    __syncthreads();

    for (int c = 0; c < 32; c++) {
        if (c + 1 < 32) ldg_chunk(c + 1);

#pragma unroll
        for (int ks = 0; ks < 2; ks++) {
            const int kc = ks * 8;
            uint32_t ah[2][4], al[2][4];
#pragma unroll
            for (int mi = 0; mi < 2; mi++) {
                int ra = (row0 + mi * 16 + g) * PST + kc + tq;
                int rb = ra + 8 * PST;
                ah[mi][0] = Ahs[ra];     ah[mi][1] = Ahs[rb];
                ah[mi][2] = Ahs[ra + 4]; ah[mi][3] = Ahs[rb + 4];
                al[mi][0] = Als[ra];     al[mi][1] = Als[rb];
                al[mi][2] = Als[ra + 4]; al[mi][3] = Als[rb + 4];
            }
#pragma unroll
            for (int ni = 0; ni < 8; ni++) {
                int rn = (col0 + ni * 8 + g) * PST + kc + tq;
                uint32_t bh0 = Whs[rn], bh1 = Whs[rn + 4];
                uint32_t bl0 = Wls[rn], bl1 = Wls[rn + 4];
#pragma unroll
                for (int mi = 0; mi < 2; mi++) {
                    mma_bf16(acc[mi][ni], ah[mi][0], ah[mi][1], ah[mi][2], ah[mi][3], bh0, bh1);
                    mma_bf16(acc[mi][ni], ah[mi][0], ah[mi][1], ah[mi][2], ah[mi][3], bl0, bl1);
                    mma_bf16(acc[mi][ni], al[mi][0], al[mi][1], al[mi][2], al[mi][3], bh0, bh1);
                }
            }
        }
        __syncthreads();
        if (c + 1 < 32) {
            sts_chunk();
            __syncthreads();
        }
    }

#pragma unroll
    for (int mi = 0; mi < 2; mi++) {
#pragma unroll
        for (int half = 0; half < 2; half++) {
            int r = bm * 128 + row0 + mi * 16 + g + half * 8;
#pragma unroll
            for (int ni = 0; ni < 8; ni++) {
                int cb = bn * 128 + col0 + ni * 8 + 2 * tq;
                float2 val = make_float2(acc[mi][ni][half * 2 + 0],
                                         acc[mi][ni][half * 2 + 1]);
                if (MODE == 0) {
                    int which = cb >> 10;          // 0:q 1:k 2:v
                    int h  = (cb >> 6) & 15;
                    int d0 = cb & 63;              // even
                    int b  = r >> 11;
                    int s  = r & 2047;
                    if (which == 2) {
                        *(float2*)(g_v + (((size_t)(b * H_ + h) * S_ + s) * DK_ + d0)) = val;
                    } else {
                        // fused RoPE on the (even, odd) pair + hi/lo split
                        int pr = d0 >> 1;
                        float invf = exp2f(-(float)pr * (13.28771237954945f / 32.0f));
                        float ang = (float)s * invf;
                        float sn, cs;
                        sincosf(ang, &sn, &cs);
                        float ev = val.x * cs - val.y * sn;
                        float od = val.x * sn + val.y * cs;
                        uint32_t hh, ll;
                        cvt_hilo(ev, od, hh, ll);
                        size_t idx = ((size_t)(b * H_ + h) * S_ + s) * 32 + pr;
                        if (which == 0) { g_qh[idx] = hh; g_ql[idx] = ll; }
                        else            { g_kh[idx] = hh; g_kl[idx] = ll; }
                    }
                } else {
                    *(float2*)(C + (size_t)r * D_ + cb) = val;
                }
            }
        }
    }
}

// ---------------------------------------------------------------------------
// V transpose + hi/lo split: g_v [b,h,s,dk] fp32 -> g_vh/g_vl [b,h][dk][s/2]
// One block per (kt, h, b): 64 s-rows x 64 dk tile.
// ---------------------------------------------------------------------------
__global__ void __launch_bounds__(256) v_convert() {
    __shared__ float ts[64 * 65];
    const int tid = threadIdx.x;
    const int kt = blockIdx.x, h = blockIdx.y, b = blockIdx.z;
    const int bh = b * H_ + h;

    const float* src = g_v + ((size_t)bh * S_ + kt * 64) * DK_;
#pragma unroll
    for (int i = 0; i < 4; i++) {
        int f = tid + i * 256;          // 1024 float4 slots
        int row = f >> 4, c4 = (f & 15) * 4;
        float4 v = *(const float4*)(src + row * DK_ + c4);
        ts[row * 65 + c4 + 0] = v.x;
        ts[row * 65 + c4 + 1] = v.y;
        ts[row * 65 + c4 + 2] = v.z;
        ts[row * 65 + c4 + 3] = v.w;
    }
    __syncthreads();

    const int w = tid >> 5, p = tid & 31;
#pragma unroll
    for (int i = 0; i < 8; i++) {
        int c = w * 8 + i;
        float x1 = ts[(2 * p) * 65 + c];
        float x2 = ts[(2 * p + 1) * 65 + c];
        uint32_t hh, ll;
        cvt_hilo(x1, x2, hh, ll);
        size_t o = ((size_t)bh * 64 + c) * (S_ / 2) + kt * 32 + p;
        g_vh[o] = hh;
        g_vl[o] = ll;
    }
}

// ---------------------------------------------------------------------------
// Flash attention, bf16x3 tensor-core, copy-only inner loop.
// BQ=BK=64, 128 thr (4 warps x 16 q-rows), causal + softcap, online softmax.
// smem: Qh,Ql,Kh,Kl [64 rows][36 pairs]; Vh,Vl [64 dk][36 pairs(kv)]
// ---------------------------------------------------------------------------
#define FST 36
#define FLASH_SMEM_BYTES (6 * 64 * FST * 4)   // 55296

__global__ void __launch_bounds__(128) flash_mma() {
    extern __shared__ uint32_t su[];
    uint32_t* Qh = su;
    uint32_t* Ql = Qh + 64*FST;
    uint32_t* Kh = Ql + 64*FST;
    uint32_t* Kl = Kh + 64*FST;
    uint32_t* Vh = Kl + 64*FST;
    uint32_t* Vl = Vh + 64*FST;

    const int tid = threadIdx.x;
    const int w = tid >> 5, l = tid & 31;
    const int g = l >> 2, tq = l & 3;
    const int q0 = blockIdx.x * 64;
    const int h = blockIdx.y, b = blockIdx.z;
    const size_t bhp = (size_t)(b * H_ + h) * S_ * 32;      // q/k pair base
    const size_t bhv = (size_t)(b * H_ + h) * 64;           // v row base

    const int crow = tid >> 1;            // 0..63
    const int cpb  = (tid & 1) * 16;      // 0 or 16

    // ---- Q tile copy (once) ----
    {
        const uint4* sh = (const uint4*)(g_qh + bhp + (size_t)(q0 + crow) * 32 + cpb);
        const uint4* sl = (const uint4*)(g_ql + bhp + (size_t)(q0 + crow) * 32 + cpb);
#pragma unroll
        for (int j = 0; j < 4; j++) {
            *(uint4*)&Qh[crow * FST + cpb + j * 4] = sh[j];
            *(uint4*)&Ql[crow * FST + cpb + j * 4] = sl[j];
        }
    }
    __syncthreads();

    uint32_t qh[4][4], ql[4][4];
#pragma unroll
    for (int kk = 0; kk < 4; kk++) {
        int ra = (w * 16 + g) * FST + kk * 8 + tq;
        int rb = ra + 8 * FST;
        qh[kk][0] = Qh[ra];     qh[kk][1] = Qh[rb];
        qh[kk][2] = Qh[ra + 4]; qh[kk][3] = Qh[rb + 4];
        ql[kk][0] = Ql[ra];     ql[kk][1] = Ql[rb];
        ql[kk][2] = Ql[ra + 4]; ql[kk][3] = Ql[rb + 4];
    }

    float m0 = -INFINITY, m1 = -INFINITY, l0s = 0.f, l1s = 0.f;
    float o[8][4];
#pragma unroll
    for (int ni = 0; ni < 8; ni++)
#pragma unroll
        for (int r = 0; r < 4; r++) o[ni][r] = 0.f;

    const int ig0 = q0 + w * 16 + g;
    const int ig1 = ig0 + 8;
    const int nkt = q0 >> 6;

    for (int kt = 0; kt <= nkt; kt++) {
        __syncthreads();
        // K tile copy
        {
            const uint4* sh = (const uint4*)(g_kh + bhp + (size_t)(kt * 64 + crow) * 32 + cpb);
            const uint4* sl = (const uint4*)(g_kl + bhp + (size_t)(kt * 64 + crow) * 32 + cpb);
#pragma unroll
            for (int j = 0; j < 4; j++) {
                *(uint4*)&Kh[crow * FST + cpb + j * 4] = sh[j];
                *(uint4*)&Kl[crow * FST + cpb + j * 4] = sl[j];
            }
        }
        // V tile copy (already transposed-packed in global)
        // Each smem row (dk) holds 32 kv-pairs: two threads per row copy
        // 16 pairs each (4 x uint4) from cpb = 0 / 16.  [round-6 bug: j<2]
        {
            const uint4* sh = (const uint4*)(g_vh + (bhv + crow) * (S_ / 2) + kt * 32 + cpb);
            const uint4* sl = (const uint4*)(g_vl + (bhv + crow) * (S_ / 2) + kt * 32 + cpb);
#pragma unroll
            for (int j = 0; j < 4; j++) {
                *(uint4*)&Vh[crow * FST + cpb + j * 4] = sh[j];
                *(uint4*)&Vl[crow * FST + cpb + j * 4] = sl[j];
            }
        }
        __syncthreads();

        // S = Q K^T (bf16x3)
        float sc[8][4];
#pragma unroll
        for (int ni = 0; ni < 8; ni++)
#pragma unroll
            for (int r = 0; r < 4; r++) sc[ni][r] = 0.f;
#pragma unroll
        for (int kk = 0; kk < 4; kk++) {
#pragma unroll
            for (int ni = 0; ni < 8; ni++) {
                int rn = (ni * 8 + g) * FST + kk * 8 + tq;
                uint32_t bh0 = Kh[rn], bh1 = Kh[rn + 4];
                uint32_t bl0 = Kl[rn], bl1 = Kl[rn + 4];
                mma_bf16(sc[ni], qh[kk][0], qh[kk][1], qh[kk][2], qh[kk][3], bh0, bh1);
                mma_bf16(sc[ni], qh[kk][0], qh[kk][1], qh[kk][2], qh[kk][3], bl0, bl1);
                mma_bf16(sc[ni], ql[kk][0], ql[kk][1], ql[kk][2], ql[kk][3], bh0, bh1);
            }
        }

        // scale + softcap + causal mask
        const bool diag = (kt == nkt);
#pragma unroll
        for (int ni = 0; ni < 8; ni++) {
            int jg = kt * 64 + ni * 8 + 2 * tq;
#pragma unroll
            for (int r = 0; r < 4; r++) {
                float v = sc[ni][r] * 0.125f;
                v = 50.0f * tanhf(v * 0.02f);
                if (diag) {
                    int col = jg + (r & 1);
                    int row = (r < 2) ? ig0 : ig1;
                    if (col > row) v = -1e30f;
                }
                sc[ni][r] = v;
            }
        }

        // online softmax
        float mx0 = -INFINITY, mx1 = -INFINITY;
#pragma unroll
        for (int ni = 0; ni < 8; ni++) {
            mx0 = fmaxf(mx0, fmaxf(sc[ni][0], sc[ni][1]));
            mx1 = fmaxf(mx1, fmaxf(sc[ni][2], sc[ni][3]));
        }
        mx0 = fmaxf(mx0, __shfl_xor_sync(0xffffffffu, mx0, 1));
        mx0 = fmaxf(mx0, __shfl_xor_sync(0xffffffffu, mx0, 2));
        mx1 = fmaxf(mx1, __shfl_xor_sync(0xffffffffu, mx1, 1));
        mx1 = fmaxf(mx1, __shfl_xor_sync(0xffffffffu, mx1, 2));
        float mn0 = fmaxf(m0, mx0), mn1 = fmaxf(m1, mx1);
        float s0 = 0.f, s1 = 0.f;
#pragma unroll
        for (int ni = 0; ni < 8; ni++) {
            sc[ni][0] = __expf(sc[ni][0] - mn0);
            sc[ni][1] = __expf(sc[ni][1] - mn0);
            sc[ni][2] = __expf(sc[ni][2] - mn1);
            sc[ni][3] = __expf(sc[ni][3] - mn1);
            s0 += sc[ni][0] + sc[ni][1];
            s1 += sc[ni][2] + sc[ni][3];
        }
        s0 += __shfl_xor_sync(0xffffffffu, s0, 1);
        s0 += __shfl_xor_sync(0xffffffffu, s0, 2);
        s1 += __shfl_xor_sync(0xffffffffu, s1, 1);
        s1 += __shfl_xor_sync(0xffffffffu, s1, 2);
        float c0 = __expf(m0 - mn0), c1 = __expf(m1 - mn1);
        l0s = l0s * c0 + s0; l1s = l1s * c1 + s1;
        m0 = mn0; m1 = mn1;
#pragma unroll
        for (int ni = 0; ni < 8; ni++) {
            o[ni][0] *= c0; o[ni][1] *= c0;
            o[ni][2] *= c1; o[ni][3] *= c1;
        }

        // pack P into A-fragments (hi/lo)
        uint32_t ph[4][4], pl[4][4];
#pragma unroll
        for (int kk = 0; kk < 4; kk++) {
            int n0 = 2 * kk, n1 = 2 * kk + 1;
            cvt_hilo(sc[n0][0], sc[n0][1], ph[kk][0], pl[kk][0]);
            cvt_hilo(sc[n0][2], sc[n0][3], ph[kk][1], pl[kk][1]);
            cvt_hilo(sc[n1][0], sc[n1][1], ph[kk][2], pl[kk][2]);
            cvt_hilo(sc[n1][2], sc[n1][3], ph[kk][3], pl[kk][3]);
        }

        // O += P V (bf16x3)
#pragma unroll
        for (int kk = 0; kk < 4; kk++) {
#pragma unroll
            for (int ni = 0; ni < 8; ni++) {
                int rn = (ni * 8 + g) * FST + kk * 8 + tq;
                uint32_t bh0 = Vh[rn], bh1 = Vh[rn + 4];
                uint32_t bl0 = Vl[rn], bl1 = Vl[rn + 4];
                mma_bf16(o[ni], ph[kk][0], ph[kk][1], ph[kk][2], ph[kk][3], bh0, bh1);
                mma_bf16(o[ni], ph[kk][0], ph[kk][1], ph[kk][2], ph[kk][3], bl0, bl1);
                mma_bf16(o[ni], pl[kk][0], pl[kk][1], pl[kk][2], pl[kk][3], bh0, bh1);
            }
        }
    }

    // epilogue: normalize, write [b,s,h,dk]
    float inv0 = 1.0f / l0s, inv1 = 1.0f / l1s;
    float* d0 = g_ao + ((size_t)(b * S_ + ig0) * H_ + h) * DK_;
    float* d1 = g_ao + ((size_t)(b * S_ + ig1) * H_ + h) * DK_;
#pragma unroll
    for (int ni = 0; ni < 8; ni++) {
        int col = ni * 8 + 2 * tq;
        *(float2*)(d0 + col) = make_float2(o[ni][0] * inv0, o[ni][1] * inv0);
        *(float2*)(d1 + col) = make_float2(o[ni][2] * inv1, o[ni][3] * inv1);
    }
}

// ---------------------------------------------------------------------------
extern "C" void kernel_launch(void* const* d_in, const int* in_sizes, int n_in,
                              void* d_out, int out_size) {
    const float* x     = (const float*)d_in[0];   // [4,2048,1024]
    const float* w_qkv = (const float*)d_in[1];   // [3072,1024]
    const float* w_out = (const float*)d_in[2];   // [1024,1024]
    float* out = (float*)d_out;                   // [4,2048,1024]

    cudaFuncSetAttribute(mm_bf16x3<0>, cudaFuncAttributeMaxDynamicSharedMemorySize, MM_SMEM_BYTES);
    cudaFuncSetAttribute(mm_bf16x3<1>, cudaFuncAttributeMaxDynamicSharedMemorySize, MM_SMEM_BYTES);
    cudaFuncSetAttribute(flash_mma,    cudaFuncAttributeMaxDynamicSharedMemorySize, FLASH_SMEM_BYTES);

    // 1) QKV projection + fused RoPE + hi/lo bf16 split
    mm_bf16x3<0><<<dim3(24, 64), 256, MM_SMEM_BYTES>>>(x, w_qkv, nullptr);

    // 2) V transpose + hi/lo split
    v_convert<<<dim3(S_/64, H_, B_), 256>>>();

    // 3) Flash attention (bf16x3 mma.sync, copy-only inner loop)
    flash_mma<<<dim3(S_/64, H_, B_), 128, FLASH_SMEM_BYTES>>>();

    // 4) Output projection
    mm_bf16x3<1><<<dim3(8, 64), 256, MM_SMEM_BYTES>>>(nullptr, w_out, out);
}

// round 8
// speedup vs baseline: 1.8600x; 1.1252x over previous
#include <cuda_runtime.h>
#include <cuda_bf16.h>
#include <cstdint>
#include <math.h>

#define B_  4
#define S_  2048
#define H_  16
#define DK_ 64
#define D_  1024

// Scratch (device globals — allocation-free rule)
__device__ float    g_v [B_*H_*S_*DK_];          // V fp32 [b,h,s,dk]
__device__ uint32_t g_qh[B_*H_*S_*32];           // packed bf16x2 pairs [b,h,s,32]
__device__ uint32_t g_ql[B_*H_*S_*32];
__device__ uint32_t g_kh[B_*H_*S_*32];
__device__ uint32_t g_kl[B_*H_*S_*32];
__device__ uint32_t g_vh[B_*H_*DK_*(S_/2)];      // pairs along s: [b,h][dk][1024]
__device__ uint32_t g_vl[B_*H_*DK_*(S_/2)];
// pre-packed GEMM operands (hi/lo bf16 pairs, row-major [rows][512])
__device__ uint32_t g_xh [B_*S_*512];            // x
__device__ uint32_t g_xl [B_*S_*512];
__device__ uint32_t g_wqh[3*D_*512];             // w_qkv
__device__ uint32_t g_wql[3*D_*512];
__device__ uint32_t g_woh[D_*512];               // w_out
__device__ uint32_t g_wol[D_*512];
__device__ uint32_t g_aoh[B_*S_*512];            // attention output (from flash)
__device__ uint32_t g_aol[B_*S_*512];

// ======================= helpers ===========================================
__device__ __forceinline__ void mma_bf16(float* c,
                                         uint32_t a0, uint32_t a1, uint32_t a2, uint32_t a3,
                                         uint32_t b0, uint32_t b1) {
    asm volatile(
        "mma.sync.aligned.m16n8k16.row.col.f32.bf16.bf16.f32 "
        "{%0,%1,%2,%3}, {%4,%5,%6,%7}, {%8,%9}, {%0,%1,%2,%3};"
        : "+f"(c[0]), "+f"(c[1]), "+f"(c[2]), "+f"(c[3])
        : "r"(a0), "r"(a1), "r"(a2), "r"(a3), "r"(b0), "r"(b1));
}

__device__ __forceinline__ void cvt_hilo(float x, float y, uint32_t& hi, uint32_t& lo) {
    __nv_bfloat162 h = __floats2bfloat162_rn(x, y);
    float hx = __bfloat162float(h.x);
    float hy = __bfloat162float(h.y);
    __nv_bfloat162 l = __floats2bfloat162_rn(x - hx, y - hy);
    hi = *(uint32_t*)&h;
    lo = *(uint32_t*)&l;
}

__device__ __forceinline__ uint32_t smem_to_u32(const void* p) {
    uint32_t a;
    asm("{ .reg .u64 t; cvta.to.shared.u64 t, %1; cvt.u32.u64 %0, t; }"
        : "=r"(a) : "l"(p));
    return a;
}
__device__ __forceinline__ void cp_async16(uint32_t dst_smem, const void* src) {
    asm volatile("cp.async.cg.shared.global [%0], [%1], 16;"
                 :: "r"(dst_smem), "l"(src) : "memory");
}
__device__ __forceinline__ void cp_commit() {
    asm volatile("cp.async.commit_group;" ::: "memory");
}
template<int N>
__device__ __forceinline__ void cp_wait() {
    asm volatile("cp.async.wait_group %0;" :: "n"(N) : "memory");
}
__device__ __forceinline__ void ldsm_x4(uint32_t& r0, uint32_t& r1, uint32_t& r2,
                                        uint32_t& r3, uint32_t addr) {
    asm volatile("ldmatrix.sync.aligned.m8n8.x4.shared.b16 {%0,%1,%2,%3}, [%4];"
                 : "=r"(r0), "=r"(r1), "=r"(r2), "=r"(r3) : "r"(addr));
}

// ---------------------------------------------------------------------------
// prep: fp32 -> packed hi/lo bf16 pairs
// ---------------------------------------------------------------------------
__global__ void prep_pack(const float* __restrict__ src, uint32_t* __restrict__ dh,
                          uint32_t* __restrict__ dl, int npairs) {
    int i = blockIdx.x * blockDim.x + threadIdx.x;
    if (i >= npairs) return;
    float2 v = ((const float2*)src)[i];
    uint32_t hh, ll;
    cvt_hilo(v.x, v.y, hh, ll);
    dh[i] = hh;
    dl[i] = ll;
}

// ---------------------------------------------------------------------------
// bf16x3 NT GEMM on pre-packed operands. CTA 128x128, chunk = 16 pairs (K=32),
// 256 thr (8 warps 4Mx2N). cp.async double buffer + ldmatrix fragments.
// MODE 0: epilogue RoPE+split scatter to q/k, V fp32; MODE 1: plain store.
// ---------------------------------------------------------------------------
#define PST 20
#define MMBUF (4 * 128 * PST)              // words per buffer (Ah|Al|Wh|Wl)
#define MM_SMEM_BYTES (2 * MMBUF * 4)      // 81920

template<int MODE>
__global__ void __launch_bounds__(256, 2) mm_ldsm(const uint32_t* __restrict__ Ah_,
                                                  const uint32_t* __restrict__ Al_,
                                                  const uint32_t* __restrict__ Wh_,
                                                  const uint32_t* __restrict__ Wl_,
                                                  float* __restrict__ C) {
    extern __shared__ uint32_t smu[];
    const int tid = threadIdx.x;
    const int w = tid >> 5, l = tid & 31;
    const int wm = w & 3, wn = w >> 2;
    const int g = l >> 2, tq = l & 3;
    const int r8 = l & 7, seg = l >> 3;
    const int bm = blockIdx.y, bn = blockIdx.x;
    const uint32_t sb = smem_to_u32(smu);

    const uint32_t* srcs[4] = {
        Ah_ + (size_t)bm * 128 * 512, Al_ + (size_t)bm * 128 * 512,
        Wh_ + (size_t)bn * 128 * 512, Wl_ + (size_t)bn * 128 * 512 };

    const int crow = tid >> 1, cpp = (tid & 1) * 8;

    auto issue = [&](int c, int p) {
        uint32_t dst = sb + (uint32_t)((p * MMBUF + crow * PST + cpp) * 4);
#pragma unroll
        for (int m = 0; m < 4; m++) {
            const uint32_t* s = srcs[m] + (size_t)crow * 512 + c * 16 + cpp;
            cp_async16(dst + m * 128 * PST * 4, s);
            cp_async16(dst + m * 128 * PST * 4 + 16, s + 4);
        }
        cp_commit();
    };

    float acc[2][8][4];
#pragma unroll
    for (int mi = 0; mi < 2; mi++)
#pragma unroll
        for (int ni = 0; ni < 8; ni++)
#pragma unroll
            for (int r = 0; r < 4; r++) acc[mi][ni][r] = 0.f;

    // per-lane ldmatrix base offsets (words, within buffer p=0, kc=0)
    // A: reg i: m0=[g][tq] m1=[g+8][tq] m2=[g][tq+4] m3=[g+8][tq+4]
    uint32_t aoff[2], boff[4];
#pragma unroll
    for (int mi = 0; mi < 2; mi++)
        aoff[mi] = (uint32_t)((wm * 32 + mi * 16 + r8 + (seg & 1) * 8) * PST + (seg >> 1) * 4);
    // B (x4 covers ni=2nj, 2nj+1): m0,m1 = b0,b1 of ni; m2,m3 = of ni+1
#pragma unroll
    for (int nj = 0; nj < 4; nj++)
        boff[nj] = (uint32_t)(2 * 128 * PST +
                              (wn * 64 + nj * 16 + r8 + (seg >> 1) * 8) * PST + (seg & 1) * 4);

    issue(0, 0);
    issue(1, 1);

    for (int c = 0; c < 32; c++) {
        const int p = c & 1;
        cp_wait<1>();
        __syncthreads();
        const uint32_t base = sb + (uint32_t)(p * MMBUF * 4);

#pragma unroll
        for (int ks = 0; ks < 2; ks++) {
            const uint32_t kcb = ks * 8 * 4;
            uint32_t ah[2][4], al[2][4];
#pragma unroll
            for (int mi = 0; mi < 2; mi++) {
                uint32_t ad = base + aoff[mi] * 4 + kcb;
                ldsm_x4(ah[mi][0], ah[mi][1], ah[mi][2], ah[mi][3], ad);
                ldsm_x4(al[mi][0], al[mi][1], al[mi][2], al[mi][3], ad + 128 * PST * 4);
            }
#pragma unroll
            for (int nj = 0; nj < 4; nj++) {
                uint32_t bd = base + boff[nj] * 4 + kcb;
                uint32_t bh[4], bl[4];
                ldsm_x4(bh[0], bh[1], bh[2], bh[3], bd);
                ldsm_x4(bl[0], bl[1], bl[2], bl[3], bd + 128 * PST * 4);
#pragma unroll
                for (int hf = 0; hf < 2; hf++) {
                    int ni = nj * 2 + hf;
#pragma unroll
                    for (int mi = 0; mi < 2; mi++) {
                        mma_bf16(acc[mi][ni], ah[mi][0], ah[mi][1], ah[mi][2], ah[mi][3],
                                 bh[hf * 2], bh[hf * 2 + 1]);
                        mma_bf16(acc[mi][ni], ah[mi][0], ah[mi][1], ah[mi][2], ah[mi][3],
                                 bl[hf * 2], bl[hf * 2 + 1]);
                        mma_bf16(acc[mi][ni], al[mi][0], al[mi][1], al[mi][2], al[mi][3],
                                 bh[hf * 2], bh[hf * 2 + 1]);
                    }
                }
            }
        }
        __syncthreads();
        if (c + 2 < 32) issue(c + 2, p);
    }

    // Epilogue
    const int row0 = wm * 32, col0 = wn * 64;
#pragma unroll
    for (int mi = 0; mi < 2; mi++) {
#pragma unroll
        for (int half = 0; half < 2; half++) {
            int r = bm * 128 + row0 + mi * 16 + g + half * 8;
#pragma unroll
            for (int ni = 0; ni < 8; ni++) {
                int cb = bn * 128 + col0 + ni * 8 + 2 * tq;
                float2 val = make_float2(acc[mi][ni][half * 2 + 0],
                                         acc[mi][ni][half * 2 + 1]);
                if (MODE == 0) {
                    int which = cb >> 10;          // 0:q 1:k 2:v
                    int h  = (cb >> 6) & 15;
                    int d0 = cb & 63;              // even
                    int b  = r >> 11;
                    int s  = r & 2047;
                    if (which == 2) {
                        *(float2*)(g_v + (((size_t)(b * H_ + h) * S_ + s) * DK_ + d0)) = val;
                    } else {
                        int pr = d0 >> 1;
                        float invf = exp2f(-(float)pr * (13.28771237954945f / 32.0f));
                        float ang = (float)s * invf;
                        float sn, cs;
                        sincosf(ang, &sn, &cs);
                        float ev = val.x * cs - val.y * sn;
                        float od = val.x * sn + val.y * cs;
                        uint32_t hh, ll;
                        cvt_hilo(ev, od, hh, ll);
                        size_t idx = ((size_t)(b * H_ + h) * S_ + s) * 32 + pr;
                        if (which == 0) { g_qh[idx] = hh; g_ql[idx] = ll; }
                        else            { g_kh[idx] = hh; g_kl[idx] = ll; }
                    }
                } else {
                    *(float2*)(C + (size_t)r * D_ + cb) = val;
                }
            }
        }
    }
}

// ---------------------------------------------------------------------------
// V transpose + hi/lo split: g_v [b,h,s,dk] fp32 -> g_vh/g_vl [b,h][dk][s/2]
// ---------------------------------------------------------------------------
__global__ void __launch_bounds__(256) v_convert() {
    __shared__ float ts[64 * 65];
    const int tid = threadIdx.x;
    const int kt = blockIdx.x, h = blockIdx.y, b = blockIdx.z;
    const int bh = b * H_ + h;

    const float* src = g_v + ((size_t)bh * S_ + kt * 64) * DK_;
#pragma unroll
    for (int i = 0; i < 4; i++) {
        int f = tid + i * 256;
        int row = f >> 4, c4 = (f & 15) * 4;
        float4 v = *(const float4*)(src + row * DK_ + c4);
        ts[row * 65 + c4 + 0] = v.x;
        ts[row * 65 + c4 + 1] = v.y;
        ts[row * 65 + c4 + 2] = v.z;
        ts[row * 65 + c4 + 3] = v.w;
    }
    __syncthreads();

    const int w = tid >> 5, p = tid & 31;
#pragma unroll
    for (int i = 0; i < 8; i++) {
        int c = w * 8 + i;
        float x1 = ts[(2 * p) * 65 + c];
        float x2 = ts[(2 * p + 1) * 65 + c];
        uint32_t hh, ll;
        cvt_hilo(x1, x2, hh, ll);
        size_t o = ((size_t)bh * 64 + c) * (S_ / 2) + kt * 32 + p;
        g_vh[o] = hh;
        g_vl[o] = ll;
    }
}

// ---------------------------------------------------------------------------
// Flash attention, bf16x3 tensor-core, copy-only inner loop.
// Epilogue writes hi/lo packed pairs to g_aoh/g_aol for the out projection.
// ---------------------------------------------------------------------------
#define FST 36
#define FLASH_SMEM_BYTES (6 * 64 * FST * 4)   // 55296

__global__ void __launch_bounds__(128) flash_mma() {
    extern __shared__ uint32_t su[];
    uint32_t* Qh = su;
    uint32_t* Ql = Qh + 64*FST;
    uint32_t* Kh = Ql + 64*FST;
    uint32_t* Kl = Kh + 64*FST;
    uint32_t* Vh = Kl + 64*FST;
    uint32_t* Vl = Vh + 64*FST;

    const int tid = threadIdx.x;
    const int w = tid >> 5, l = tid & 31;
    const int g = l >> 2, tq = l & 3;
    const int q0 = blockIdx.x * 64;
    const int h = blockIdx.y, b = blockIdx.z;
    const size_t bhp = (size_t)(b * H_ + h) * S_ * 32;
    const size_t bhv = (size_t)(b * H_ + h) * 64;

    const int crow = tid >> 1;
    const int cpb  = (tid & 1) * 16;

    {
        const uint4* sh = (const uint4*)(g_qh + bhp + (size_t)(q0 + crow) * 32 + cpb);
        const uint4* sl = (const uint4*)(g_ql + bhp + (size_t)(q0 + crow) * 32 + cpb);
#pragma unroll
        for (int j = 0; j < 4; j++) {
            *(uint4*)&Qh[crow * FST + cpb + j * 4] = sh[j];
            *(uint4*)&Ql[crow * FST + cpb + j * 4] = sl[j];
        }
    }
    __syncthreads();

    uint32_t qh[4][4], ql[4][4];
#pragma unroll
    for (int kk = 0; kk < 4; kk++) {
        int ra = (w * 16 + g) * FST + kk * 8 + tq;
        int rb = ra + 8 * FST;
        qh[kk][0] = Qh[ra];     qh[kk][1] = Qh[rb];
        qh[kk][2] = Qh[ra + 4]; qh[kk][3] = Qh[rb + 4];
        ql[kk][0] = Ql[ra];     ql[kk][1] = Ql[rb];
        ql[kk][2] = Ql[ra + 4]; ql[kk][3] = Ql[rb + 4];
    }

    float m0 = -INFINITY, m1 = -INFINITY, l0s = 0.f, l1s = 0.f;
    float o[8][4];
#pragma unroll
    for (int ni = 0; ni < 8; ni++)
#pragma unroll
        for (int r = 0; r < 4; r++) o[ni][r] = 0.f;

    const int ig0 = q0 + w * 16 + g;
    const int ig1 = ig0 + 8;
    const int nkt = q0 >> 6;

    for (int kt = 0; kt <= nkt; kt++) {
        __syncthreads();
        {
            const uint4* sh = (const uint4*)(g_kh + bhp + (size_t)(kt * 64 + crow) * 32 + cpb);
            const uint4* sl = (const uint4*)(g_kl + bhp + (size_t)(kt * 64 + crow) * 32 + cpb);
#pragma unroll
            for (int j = 0; j < 4; j++) {
                *(uint4*)&Kh[crow * FST + cpb + j * 4] = sh[j];
                *(uint4*)&Kl[crow * FST + cpb + j * 4] = sl[j];
            }
        }
        {
            const uint4* sh = (const uint4*)(g_vh + (bhv + crow) * (S_ / 2) + kt * 32 + cpb);
            const uint4* sl = (const uint4*)(g_vl + (bhv + crow) * (S_ / 2) + kt * 32 + cpb);
#pragma unroll
            for (int j = 0; j < 4; j++) {
                *(uint4*)&Vh[crow * FST + cpb + j * 4] = sh[j];
                *(uint4*)&Vl[crow * FST + cpb + j * 4] = sl[j];
            }
        }
        __syncthreads();

        float sc[8][4];
#pragma unroll
        for (int ni = 0; ni < 8; ni++)
#pragma unroll
            for (int r = 0; r < 4; r++) sc[ni][r] = 0.f;
#pragma unroll
        for (int kk = 0; kk < 4; kk++) {
#pragma unroll
            for (int ni = 0; ni < 8; ni++) {
                int rn = (ni * 8 + g) * FST + kk * 8 + tq;
                uint32_t bh0 = Kh[rn], bh1 = Kh[rn + 4];
                uint32_t bl0 = Kl[rn], bl1 = Kl[rn + 4];
                mma_bf16(sc[ni], qh[kk][0], qh[kk][1], qh[kk][2], qh[kk][3], bh0, bh1);
                mma_bf16(sc[ni], qh[kk][0], qh[kk][1], qh[kk][2], qh[kk][3], bl0, bl1);
                mma_bf16(sc[ni], ql[kk][0], ql[kk][1], ql[kk][2], ql[kk][3], bh0, bh1);
            }
        }

        const bool diag = (kt == nkt);
#pragma unroll
        for (int ni = 0; ni < 8; ni++) {
            int jg = kt * 64 + ni * 8 + 2 * tq;
#pragma unroll
            for (int r = 0; r < 4; r++) {
                float v = sc[ni][r] * 0.125f;
                v = 50.0f * tanhf(v * 0.02f);
                if (diag) {
                    int col = jg + (r & 1);
                    int row = (r < 2) ? ig0 : ig1;
                    if (col > row) v = -1e30f;
                }
                sc[ni][r] = v;
            }
        }

        float mx0 = -INFINITY, mx1 = -INFINITY;
#pragma unroll
        for (int ni = 0; ni < 8; ni++) {
            mx0 = fmaxf(mx0, fmaxf(sc[ni][0], sc[ni][1]));
            mx1 = fmaxf(mx1, fmaxf(sc[ni][2], sc[ni][3]));
        }
        mx0 = fmaxf(mx0, __shfl_xor_sync(0xffffffffu, mx0, 1));
        mx0 = fmaxf(mx0, __shfl_xor_sync(0xffffffffu, mx0, 2));
        mx1 = fmaxf(mx1, __shfl_xor_sync(0xffffffffu, mx1, 1));
        mx1 = fmaxf(mx1, __shfl_xor_sync(0xffffffffu, mx1, 2));
        float mn0 = fmaxf(m0, mx0), mn1 = fmaxf(m1, mx1);
        float s0 = 0.f, s1 = 0.f;
#pragma unroll
        for (int ni = 0; ni < 8; ni++) {
            sc[ni][0] = __expf(sc[ni][0] - mn0);
            sc[ni][1] = __expf(sc[ni][1] - mn0);
            sc[ni][2] = __expf(sc[ni][2] - mn1);
            sc[ni][3] = __expf(sc[ni][3] - mn1);
            s0 += sc[ni][0] + sc[ni][1];
            s1 += sc[ni][2] + sc[ni][3];
        }
        s0 += __shfl_xor_sync(0xffffffffu, s0, 1);
        s0 += __shfl_xor_sync(0xffffffffu, s0, 2);
        s1 += __shfl_xor_sync(0xffffffffu, s1, 1);
        s1 += __shfl_xor_sync(0xffffffffu, s1, 2);
        float c0 = __expf(m0 - mn0), c1 = __expf(m1 - mn1);
        l0s = l0s * c0 + s0; l1s = l1s * c1 + s1;
        m0 = mn0; m1 = mn1;
#pragma unroll
        for (int ni = 0; ni < 8; ni++) {
            o[ni][0] *= c0; o[ni][1] *= c0;
            o[ni][2] *= c1; o[ni][3] *= c1;
        }

        uint32_t ph[4][4], pl[4][4];
#pragma unroll
        for (int kk = 0; kk < 4; kk++) {
            int n0 = 2 * kk, n1 = 2 * kk + 1;
            cvt_hilo(sc[n0][0], sc[n0][1], ph[kk][0], pl[kk][0]);
            cvt_hilo(sc[n0][2], sc[n0][3], ph[kk][1], pl[kk][1]);
            cvt_hilo(sc[n1][0], sc[n1][1], ph[kk][2], pl[kk][2]);
            cvt_hilo(sc[n1][2], sc[n1][3], ph[kk][3], pl[kk][3]);
        }

#pragma unroll
        for (int kk = 0; kk < 4; kk++) {
#pragma unroll
            for (int ni = 0; ni < 8; ni++) {
                int rn = (ni * 8 + g) * FST + kk * 8 + tq;
                uint32_t bh0 = Vh[rn], bh1 = Vh[rn + 4];
                uint32_t bl0 = Vl[rn], bl1 = Vl[rn + 4];
                mma_bf16(o[ni], ph[kk][0], ph[kk][1], ph[kk][2], ph[kk][3], bh0, bh1);
                mma_bf16(o[ni], ph[kk][0], ph[kk][1], ph[kk][2], ph[kk][3], bl0, bl1);
                mma_bf16(o[ni], pl[kk][0], pl[kk][1], pl[kk][2], pl[kk][3], bh0, bh1);
            }
        }
    }

    // epilogue: normalize, split hi/lo, write packed pairs [b,s][512]
    float inv0 = 1.0f / l0s, inv1 = 1.0f / l1s;
    size_t r0b = (size_t)(b * S_ + ig0) * 512 + h * 32;
    size_t r1b = (size_t)(b * S_ + ig1) * 512 + h * 32;
#pragma unroll
    for (int ni = 0; ni < 8; ni++) {
        int pr = ni * 4 + tq;
        uint32_t hh, ll;
        cvt_hilo(o[ni][0] * inv0, o[ni][1] * inv0, hh, ll);
        g_aoh[r0b + pr] = hh; g_aol[r0b + pr] = ll;
        cvt_hilo(o[ni][2] * inv1, o[ni][3] * inv1, hh, ll);
        g_aoh[r1b + pr] = hh; g_aol[r1b + pr] = ll;
    }
}

// ---------------------------------------------------------------------------
extern "C" void kernel_launch(void* const* d_in, const int* in_sizes, int n_in,
                              void* d_out, int out_size) {
    const float* x     = (const float*)d_in[0];   // [4,2048,1024]
    const float* w_qkv = (const float*)d_in[1];   // [3072,1024]
    const float* w_out = (const float*)d_in[2];   // [1024,1024]
    float* out = (float*)d_out;                   // [4,2048,1024]

    cudaFuncSetAttribute(mm_ldsm<0>, cudaFuncAttributeMaxDynamicSharedMemorySize, MM_SMEM_BYTES);
    cudaFuncSetAttribute(mm_ldsm<1>, cudaFuncAttributeMaxDynamicSharedMemorySize, MM_SMEM_BYTES);
    cudaFuncSetAttribute(flash_mma,  cudaFuncAttributeMaxDynamicSharedMemorySize, FLASH_SMEM_BYTES);

    uint32_t *xh, *xl, *wqh, *wql, *woh, *wol, *aoh, *aol;
    cudaGetSymbolAddress((void**)&xh,  g_xh);  cudaGetSymbolAddress((void**)&xl,  g_xl);
    cudaGetSymbolAddress((void**)&wqh, g_wqh); cudaGetSymbolAddress((void**)&wql, g_wql);
    cudaGetSymbolAddress((void**)&woh, g_woh); cudaGetSymbolAddress((void**)&wol, g_wol);
    cudaGetSymbolAddress((void**)&aoh, g_aoh); cudaGetSymbolAddress((void**)&aol, g_aol);

    // 0) pre-pack operands to hi/lo bf16 pairs
    prep_pack<<<(B_*S_*512 + 255) / 256, 256>>>(x,     xh,  xl,  B_*S_*512);
    prep_pack<<<(3*D_*512  + 255) / 256, 256>>>(w_qkv, wqh, wql, 3*D_*512);
    prep_pack<<<(D_*512    + 255) / 256, 256>>>(w_out, woh, wol, D_*512);

    // 1) QKV projection + fused RoPE + hi/lo split
    mm_ldsm<0><<<dim3(24, 64), 256, MM_SMEM_BYTES>>>(xh, xl, wqh, wql, nullptr);

    // 2) V transpose + hi/lo split
    v_convert<<<dim3(S_/64, H_, B_), 256>>>();

    // 3) Flash attention
    flash_mma<<<dim3(S_/64, H_, B_), 128, FLASH_SMEM_BYTES>>>();

    // 4) Output projection
    mm_ldsm<1><<<dim3(8, 64), 256, MM_SMEM_BYTES>>>(aoh, aol, woh, wol, out);
}

// round 9
// speedup vs baseline: 1.9053x; 1.0243x over previous
#include <cuda_runtime.h>
#include <cuda_bf16.h>
#include <cstdint>
#include <math.h>

#define B_  4
#define S_  2048
#define H_  16
#define DK_ 64
#define D_  1024

// Scratch (device globals — allocation-free rule)
__device__ float    g_v [B_*H_*S_*DK_];          // V fp32 [b,h,s,dk]
__device__ uint32_t g_qh[B_*H_*S_*32];           // packed bf16x2 pairs [b,h,s,32]
__device__ uint32_t g_ql[B_*H_*S_*32];
__device__ uint32_t g_kh[B_*H_*S_*32];
__device__ uint32_t g_kl[B_*H_*S_*32];
__device__ uint32_t g_vh[B_*H_*DK_*(S_/2)];      // pairs along s: [b,h][dk][1024]
__device__ uint32_t g_vl[B_*H_*DK_*(S_/2)];
// pre-packed GEMM operands (hi/lo bf16 pairs, row-major [rows][512])
__device__ uint32_t g_xh [B_*S_*512];
__device__ uint32_t g_xl [B_*S_*512];
__device__ uint32_t g_wqh[3*D_*512];
__device__ uint32_t g_wql[3*D_*512];
__device__ uint32_t g_woh[D_*512];
__device__ uint32_t g_wol[D_*512];
__device__ uint32_t g_aoh[B_*S_*512];            // attention output (packed)
__device__ uint32_t g_aol[B_*S_*512];

// ======================= helpers ===========================================
__device__ __forceinline__ void mma_bf16(float* c,
                                         uint32_t a0, uint32_t a1, uint32_t a2, uint32_t a3,
                                         uint32_t b0, uint32_t b1) {
    asm volatile(
        "mma.sync.aligned.m16n8k16.row.col.f32.bf16.bf16.f32 "
        "{%0,%1,%2,%3}, {%4,%5,%6,%7}, {%8,%9}, {%0,%1,%2,%3};"
        : "+f"(c[0]), "+f"(c[1]), "+f"(c[2]), "+f"(c[3])
        : "r"(a0), "r"(a1), "r"(a2), "r"(a3), "r"(b0), "r"(b1));
}

__device__ __forceinline__ void cvt_hilo(float x, float y, uint32_t& hi, uint32_t& lo) {
    __nv_bfloat162 h = __floats2bfloat162_rn(x, y);
    float hx = __bfloat162float(h.x);
    float hy = __bfloat162float(h.y);
    __nv_bfloat162 l = __floats2bfloat162_rn(x - hx, y - hy);
    hi = *(uint32_t*)&h;
    lo = *(uint32_t*)&l;
}

__device__ __forceinline__ uint32_t smem_to_u32(const void* p) {
    uint32_t a;
    asm("{ .reg .u64 t; cvta.to.shared.u64 t, %1; cvt.u32.u64 %0, t; }"
        : "=r"(a) : "l"(p));
    return a;
}
__device__ __forceinline__ void cp_async16(uint32_t dst_smem, const void* src) {
    asm volatile("cp.async.cg.shared.global [%0], [%1], 16;"
                 :: "r"(dst_smem), "l"(src) : "memory");
}
__device__ __forceinline__ void cp_commit() {
    asm volatile("cp.async.commit_group;" ::: "memory");
}
template<int N>
__device__ __forceinline__ void cp_wait() {
    asm volatile("cp.async.wait_group %0;" :: "n"(N) : "memory");
}
__device__ __forceinline__ void ldsm_x4(uint32_t& r0, uint32_t& r1, uint32_t& r2,
                                        uint32_t& r3, uint32_t addr) {
    asm volatile("ldmatrix.sync.aligned.m8n8.x4.shared.b16 {%0,%1,%2,%3}, [%4];"
                 : "=r"(r0), "=r"(r1), "=r"(r2), "=r"(r3) : "r"(addr));
}

// ---------------------------------------------------------------------------
// prep: fp32 -> packed hi/lo bf16 pairs
// ---------------------------------------------------------------------------
__global__ void prep_pack(const float* __restrict__ src, uint32_t* __restrict__ dh,
                          uint32_t* __restrict__ dl, int npairs) {
    int i = blockIdx.x * blockDim.x + threadIdx.x;
    if (i >= npairs) return;
    float2 v = ((const float2*)src)[i];
    uint32_t hh, ll;
    cvt_hilo(v.x, v.y, hh, ll);
    dh[i] = hh;
    dl[i] = ll;
}

// ---------------------------------------------------------------------------
// bf16x3 NT GEMM on pre-packed operands (unchanged from round 8).
// ---------------------------------------------------------------------------
#define PST 20
#define MMBUF (4 * 128 * PST)
#define MM_SMEM_BYTES (2 * MMBUF * 4)      // 81920

template<int MODE>
__global__ void __launch_bounds__(256, 2) mm_ldsm(const uint32_t* __restrict__ Ah_,
                                                  const uint32_t* __restrict__ Al_,
                                                  const uint32_t* __restrict__ Wh_,
                                                  const uint32_t* __restrict__ Wl_,
                                                  float* __restrict__ C) {
    extern __shared__ uint32_t smu[];
    const int tid = threadIdx.x;
    const int w = tid >> 5, l = tid & 31;
    const int wm = w & 3, wn = w >> 2;
    const int g = l >> 2, tq = l & 3;
    const int r8 = l & 7, seg = l >> 3;
    const int bm = blockIdx.y, bn = blockIdx.x;
    const uint32_t sb = smem_to_u32(smu);

    const uint32_t* srcs[4] = {
        Ah_ + (size_t)bm * 128 * 512, Al_ + (size_t)bm * 128 * 512,
        Wh_ + (size_t)bn * 128 * 512, Wl_ + (size_t)bn * 128 * 512 };

    const int crow = tid >> 1, cpp = (tid & 1) * 8;

    auto issue = [&](int c, int p) {
        uint32_t dst = sb + (uint32_t)((p * MMBUF + crow * PST + cpp) * 4);
#pragma unroll
        for (int m = 0; m < 4; m++) {
            const uint32_t* s = srcs[m] + (size_t)crow * 512 + c * 16 + cpp;
            cp_async16(dst + m * 128 * PST * 4, s);
            cp_async16(dst + m * 128 * PST * 4 + 16, s + 4);
        }
        cp_commit();
    };

    float acc[2][8][4];
#pragma unroll
    for (int mi = 0; mi < 2; mi++)
#pragma unroll
        for (int ni = 0; ni < 8; ni++)
#pragma unroll
            for (int r = 0; r < 4; r++) acc[mi][ni][r] = 0.f;

    uint32_t aoff[2], boff[4];
#pragma unroll
    for (int mi = 0; mi < 2; mi++)
        aoff[mi] = (uint32_t)((wm * 32 + mi * 16 + r8 + (seg & 1) * 8) * PST + (seg >> 1) * 4);
#pragma unroll
    for (int nj = 0; nj < 4; nj++)
        boff[nj] = (uint32_t)(2 * 128 * PST +
                              (wn * 64 + nj * 16 + r8 + (seg >> 1) * 8) * PST + (seg & 1) * 4);

    issue(0, 0);
    issue(1, 1);

    for (int c = 0; c < 32; c++) {
        const int p = c & 1;
        cp_wait<1>();
        __syncthreads();
        const uint32_t base = sb + (uint32_t)(p * MMBUF * 4);

#pragma unroll
        for (int ks = 0; ks < 2; ks++) {
            const uint32_t kcb = ks * 8 * 4;
            uint32_t ah[2][4], al[2][4];
#pragma unroll
            for (int mi = 0; mi < 2; mi++) {
                uint32_t ad = base + aoff[mi] * 4 + kcb;
                ldsm_x4(ah[mi][0], ah[mi][1], ah[mi][2], ah[mi][3], ad);
                ldsm_x4(al[mi][0], al[mi][1], al[mi][2], al[mi][3], ad + 128 * PST * 4);
            }
#pragma unroll
            for (int nj = 0; nj < 4; nj++) {
                uint32_t bd = base + boff[nj] * 4 + kcb;
                uint32_t bh[4], bl[4];
                ldsm_x4(bh[0], bh[1], bh[2], bh[3], bd);
                ldsm_x4(bl[0], bl[1], bl[2], bl[3], bd + 128 * PST * 4);
#pragma unroll
                for (int hf = 0; hf < 2; hf++) {
                    int ni = nj * 2 + hf;
#pragma unroll
                    for (int mi = 0; mi < 2; mi++) {
                        mma_bf16(acc[mi][ni], ah[mi][0], ah[mi][1], ah[mi][2], ah[mi][3],
                                 bh[hf * 2], bh[hf * 2 + 1]);
                        mma_bf16(acc[mi][ni], ah[mi][0], ah[mi][1], ah[mi][2], ah[mi][3],
                                 bl[hf * 2], bl[hf * 2 + 1]);
                        mma_bf16(acc[mi][ni], al[mi][0], al[mi][1], al[mi][2], al[mi][3],
                                 bh[hf * 2], bh[hf * 2 + 1]);
                    }
                }
            }
        }
        __syncthreads();
        if (c + 2 < 32) issue(c + 2, p);
    }

    const int row0 = wm * 32, col0 = wn * 64;
#pragma unroll
    for (int mi = 0; mi < 2; mi++) {
#pragma unroll
        for (int half = 0; half < 2; half++) {
            int r = bm * 128 + row0 + mi * 16 + g + half * 8;
#pragma unroll
            for (int ni = 0; ni < 8; ni++) {
                int cb = bn * 128 + col0 + ni * 8 + 2 * tq;
                float2 val = make_float2(acc[mi][ni][half * 2 + 0],
                                         acc[mi][ni][half * 2 + 1]);
                if (MODE == 0) {
                    int which = cb >> 10;
                    int h  = (cb >> 6) & 15;
                    int d0 = cb & 63;
                    int b  = r >> 11;
                    int s  = r & 2047;
                    if (which == 2) {
                        *(float2*)(g_v + (((size_t)(b * H_ + h) * S_ + s) * DK_ + d0)) = val;
                    } else {
                        int pr = d0 >> 1;
                        float invf = exp2f(-(float)pr * (13.28771237954945f / 32.0f));
                        float ang = (float)s * invf;
                        float sn, cs;
                        sincosf(ang, &sn, &cs);
                        float ev = val.x * cs - val.y * sn;
                        float od = val.x * sn + val.y * cs;
                        uint32_t hh, ll;
                        cvt_hilo(ev, od, hh, ll);
                        size_t idx = ((size_t)(b * H_ + h) * S_ + s) * 32 + pr;
                        if (which == 0) { g_qh[idx] = hh; g_ql[idx] = ll; }
                        else            { g_kh[idx] = hh; g_kl[idx] = ll; }
                    }
                } else {
                    *(float2*)(C + (size_t)r * D_ + cb) = val;
                }
            }
        }
    }
}

// ---------------------------------------------------------------------------
// V transpose + hi/lo split (unchanged)
// ---------------------------------------------------------------------------
__global__ void __launch_bounds__(256) v_convert() {
    __shared__ float ts[64 * 65];
    const int tid = threadIdx.x;
    const int kt = blockIdx.x, h = blockIdx.y, b = blockIdx.z;
    const int bh = b * H_ + h;

    const float* src = g_v + ((size_t)bh * S_ + kt * 64) * DK_;
#pragma unroll
    for (int i = 0; i < 4; i++) {
        int f = tid + i * 256;
        int row = f >> 4, c4 = (f & 15) * 4;
        float4 v = *(const float4*)(src + row * DK_ + c4);
        ts[row * 65 + c4 + 0] = v.x;
        ts[row * 65 + c4 + 1] = v.y;
        ts[row * 65 + c4 + 2] = v.z;
        ts[row * 65 + c4 + 3] = v.w;
    }
    __syncthreads();

    const int w = tid >> 5, p = tid & 31;
#pragma unroll
    for (int i = 0; i < 8; i++) {
        int c = w * 8 + i;
        float x1 = ts[(2 * p) * 65 + c];
        float x2 = ts[(2 * p + 1) * 65 + c];
        uint32_t hh, ll;
        cvt_hilo(x1, x2, hh, ll);
        size_t o = ((size_t)bh * 64 + c) * (S_ / 2) + kt * 32 + p;
        g_vh[o] = hh;
        g_vl[o] = ll;
    }
}

// ---------------------------------------------------------------------------
// Flash attention v2: BQ=128, 256 thr (8 warps x 16 q-rows), cp.async
// double-buffered KV, one __syncthreads per tile, per-warp tile skip.
// smem: Qh,Ql [128][36]; 2 KV stages of (Kh,Kl,Vh,Vl)[64][36].
// ---------------------------------------------------------------------------
#define FST 36
#define FQW  (2 * 128 * FST)          // Q words (9216)
#define FKVW (4 * 64 * FST)           // per-stage words (9216)
#define FLASH_SMEM_BYTES ((FQW + 2 * FKVW) * 4)   // 110592

__global__ void __launch_bounds__(256, 2) flash_mma() {
    extern __shared__ uint32_t su[];
    uint32_t* Qh = su;                 // [128][36]
    uint32_t* Ql = su + 128 * FST;

    const int tid = threadIdx.x;
    const int w = tid >> 5, l = tid & 31;
    const int g = l >> 2, tq = l & 3;
    const int q0 = (int)(gridDim.x - 1 - blockIdx.x) * 128;   // long CTAs first
    const int h = blockIdx.y, b = blockIdx.z;
    const size_t bhp = (size_t)(b * H_ + h) * S_ * 32;
    const size_t bhv = (size_t)(b * H_ + h) * 64;
    const uint32_t sb = smem_to_u32(su);

    // KV copy mapping: 256 thr, row = tid>>2 (0..63), 8-pair quarter
    const int kvrow = tid >> 2;
    const int kvq   = (tid & 3) * 8;

    auto issue_kv = [&](int kt, int s) {
        uint32_t base = sb + (uint32_t)((FQW + s * FKVW + kvrow * FST + kvq) * 4);
        const uint32_t* k_h = g_kh + bhp + (size_t)(kt * 64 + kvrow) * 32 + kvq;
        const uint32_t* k_l = g_kl + bhp + (size_t)(kt * 64 + kvrow) * 32 + kvq;
        const uint32_t* v_h = g_vh + (bhv + kvrow) * (S_ / 2) + kt * 32 + kvq;
        const uint32_t* v_l = g_vl + (bhv + kvrow) * (S_ / 2) + kt * 32 + kvq;
        cp_async16(base,                      k_h);
        cp_async16(base + 16,                 k_h + 4);
        cp_async16(base + 64*FST*4,           k_l);
        cp_async16(base + 64*FST*4 + 16,      k_l + 4);
        cp_async16(base + 2*64*FST*4,         v_h);
        cp_async16(base + 2*64*FST*4 + 16,    v_h + 4);
        cp_async16(base + 3*64*FST*4,         v_l);
        cp_async16(base + 3*64*FST*4 + 16,    v_l + 4);
        cp_commit();
    };

    // prologue: KV tile 0 + Q tile via cp.async
    issue_kv(0, 0);
    {
        int row = tid >> 1, pb = (tid & 1) * 16;
        const uint32_t* sh = g_qh + bhp + (size_t)(q0 + row) * 32 + pb;
        const uint32_t* sl = g_ql + bhp + (size_t)(q0 + row) * 32 + pb;
        uint32_t d = sb + (uint32_t)((row * FST + pb) * 4);
#pragma unroll
        for (int j = 0; j < 4; j++) {
            cp_async16(d + j * 16,                 sh + j * 4);
            cp_async16(d + 128*FST*4 + j * 16,     sl + j * 4);
        }
        cp_commit();
    }
    cp_wait<0>();
    __syncthreads();

    // hoist Q fragments for this warp's 16 rows
    uint32_t qh[4][4], ql[4][4];
#pragma unroll
    for (int kk = 0; kk < 4; kk++) {
        int ra = (w * 16 + g) * FST + kk * 8 + tq;
        int rb = ra + 8 * FST;
        qh[kk][0] = Qh[ra];     qh[kk][1] = Qh[rb];
        qh[kk][2] = Qh[ra + 4]; qh[kk][3] = Qh[rb + 4];
        ql[kk][0] = Ql[ra];     ql[kk][1] = Ql[rb];
        ql[kk][2] = Ql[ra + 4]; ql[kk][3] = Ql[rb + 4];
    }

    float m0 = -INFINITY, m1 = -INFINITY, l0s = 0.f, l1s = 0.f;
    float o[8][4];
#pragma unroll
    for (int ni = 0; ni < 8; ni++)
#pragma unroll
        for (int r = 0; r < 4; r++) o[ni][r] = 0.f;

    const int ig0 = q0 + w * 16 + g;
    const int ig1 = ig0 + 8;
    const int rowmax = q0 + w * 16 + 15;
    const int nkt = (q0 + 127) >> 6;

    for (int kt = 0; kt <= nkt; kt++) {
        const int p = kt & 1;
        if (kt > 0) cp_wait<0>();
        __syncthreads();
        if (kt < nkt) issue_kv(kt + 1, p ^ 1);   // overlaps compute below

        if (kt * 64 <= rowmax) {                 // per-warp tile skip
            uint32_t* Kh_ = su + FQW + p * FKVW;
            uint32_t* Kl_ = Kh_ + 64 * FST;
            uint32_t* Vh_ = Kh_ + 2 * 64 * FST;
            uint32_t* Vl_ = Kh_ + 3 * 64 * FST;

            // S = Q K^T (bf16x3)
            float sc[8][4];
#pragma unroll
            for (int ni = 0; ni < 8; ni++)
#pragma unroll
                for (int r = 0; r < 4; r++) sc[ni][r] = 0.f;
#pragma unroll
            for (int kk = 0; kk < 4; kk++) {
#pragma unroll
                for (int ni = 0; ni < 8; ni++) {
                    int rn = (ni * 8 + g) * FST + kk * 8 + tq;
                    uint32_t bh0 = Kh_[rn], bh1 = Kh_[rn + 4];
                    uint32_t bl0 = Kl_[rn], bl1 = Kl_[rn + 4];
                    mma_bf16(sc[ni], qh[kk][0], qh[kk][1], qh[kk][2], qh[kk][3], bh0, bh1);
                    mma_bf16(sc[ni], qh[kk][0], qh[kk][1], qh[kk][2], qh[kk][3], bl0, bl1);
                    mma_bf16(sc[ni], ql[kk][0], ql[kk][1], ql[kk][2], ql[kk][3], bh0, bh1);
                }
            }

            // scale + softcap + causal mask (per-warp diag)
            const bool diag = (kt * 64 + 63) > ig0;
#pragma unroll
            for (int ni = 0; ni < 8; ni++) {
                int jg = kt * 64 + ni * 8 + 2 * tq;
#pragma unroll
                for (int r = 0; r < 4; r++) {
                    float v = sc[ni][r] * 0.125f;
                    v = 50.0f * tanhf(v * 0.02f);
                    if (diag) {
                        int col = jg + (r & 1);
                        int row = (r < 2) ? ig0 : ig1;
                        if (col > row) v = -1e30f;
                    }
                    sc[ni][r] = v;
                }
            }

            // online softmax
            float mx0 = -INFINITY, mx1 = -INFINITY;
#pragma unroll
            for (int ni = 0; ni < 8; ni++) {
                mx0 = fmaxf(mx0, fmaxf(sc[ni][0], sc[ni][1]));
                mx1 = fmaxf(mx1, fmaxf(sc[ni][2], sc[ni][3]));
            }
            mx0 = fmaxf(mx0, __shfl_xor_sync(0xffffffffu, mx0, 1));
            mx0 = fmaxf(mx0, __shfl_xor_sync(0xffffffffu, mx0, 2));
            mx1 = fmaxf(mx1, __shfl_xor_sync(0xffffffffu, mx1, 1));
            mx1 = fmaxf(mx1, __shfl_xor_sync(0xffffffffu, mx1, 2));
            float mn0 = fmaxf(m0, mx0), mn1 = fmaxf(m1, mx1);
            float s0 = 0.f, s1 = 0.f;
#pragma unroll
            for (int ni = 0; ni < 8; ni++) {
                sc[ni][0] = __expf(sc[ni][0] - mn0);
                sc[ni][1] = __expf(sc[ni][1] - mn0);
                sc[ni][2] = __expf(sc[ni][2] - mn1);
                sc[ni][3] = __expf(sc[ni][3] - mn1);
                s0 += sc[ni][0] + sc[ni][1];
                s1 += sc[ni][2] + sc[ni][3];
            }
            s0 += __shfl_xor_sync(0xffffffffu, s0, 1);
            s0 += __shfl_xor_sync(0xffffffffu, s0, 2);
            s1 += __shfl_xor_sync(0xffffffffu, s1, 1);
            s1 += __shfl_xor_sync(0xffffffffu, s1, 2);
            float c0 = __expf(m0 - mn0), c1 = __expf(m1 - mn1);
            l0s = l0s * c0 + s0; l1s = l1s * c1 + s1;
            m0 = mn0; m1 = mn1;
#pragma unroll
            for (int ni = 0; ni < 8; ni++) {
                o[ni][0] *= c0; o[ni][1] *= c0;
                o[ni][2] *= c1; o[ni][3] *= c1;
            }

            // pack P into A-fragments (hi/lo)
            uint32_t ph[4][4], pl[4][4];
#pragma unroll
            for (int kk = 0; kk < 4; kk++) {
                int n0 = 2 * kk, n1 = 2 * kk + 1;
                cvt_hilo(sc[n0][0], sc[n0][1], ph[kk][0], pl[kk][0]);
                cvt_hilo(sc[n0][2], sc[n0][3], ph[kk][1], pl[kk][1]);
                cvt_hilo(sc[n1][0], sc[n1][1], ph[kk][2], pl[kk][2]);
                cvt_hilo(sc[n1][2], sc[n1][3], ph[kk][3], pl[kk][3]);
            }

            // O += P V (bf16x3)
#pragma unroll
            for (int kk = 0; kk < 4; kk++) {
#pragma unroll
                for (int ni = 0; ni < 8; ni++) {
                    int rn = (ni * 8 + g) * FST + kk * 8 + tq;
                    uint32_t bh0 = Vh_[rn], bh1 = Vh_[rn + 4];
                    uint32_t bl0 = Vl_[rn], bl1 = Vl_[rn + 4];
                    mma_bf16(o[ni], ph[kk][0], ph[kk][1], ph[kk][2], ph[kk][3], bh0, bh1);
                    mma_bf16(o[ni], ph[kk][0], ph[kk][1], ph[kk][2], ph[kk][3], bl0, bl1);
                    mma_bf16(o[ni], pl[kk][0], pl[kk][1], pl[kk][2], pl[kk][3], bh0, bh1);
                }
            }
        }
    }

    // epilogue: normalize, split hi/lo, write packed pairs [b,s][512]
    float inv0 = 1.0f / l0s, inv1 = 1.0f / l1s;
    size_t r0b = (size_t)(b * S_ + ig0) * 512 + h * 32;
    size_t r1b = (size_t)(b * S_ + ig1) * 512 + h * 32;
#pragma unroll
    for (int ni = 0; ni < 8; ni++) {
        int pr = ni * 4 + tq;
        uint32_t hh, ll;
        cvt_hilo(o[ni][0] * inv0, o[ni][1] * inv0, hh, ll);
        g_aoh[r0b + pr] = hh; g_aol[r0b + pr] = ll;
        cvt_hilo(o[ni][2] * inv1, o[ni][3] * inv1, hh, ll);
        g_aoh[r1b + pr] = hh; g_aol[r1b + pr] = ll;
    }
}

// ---------------------------------------------------------------------------
extern "C" void kernel_launch(void* const* d_in, const int* in_sizes, int n_in,
                              void* d_out, int out_size) {
    const float* x     = (const float*)d_in[0];   // [4,2048,1024]
    const float* w_qkv = (const float*)d_in[1];   // [3072,1024]
    const float* w_out = (const float*)d_in[2];   // [1024,1024]
    float* out = (float*)d_out;                   // [4,2048,1024]

    cudaFuncSetAttribute(mm_ldsm<0>, cudaFuncAttributeMaxDynamicSharedMemorySize, MM_SMEM_BYTES);
    cudaFuncSetAttribute(mm_ldsm<1>, cudaFuncAttributeMaxDynamicSharedMemorySize, MM_SMEM_BYTES);
    cudaFuncSetAttribute(flash_mma,  cudaFuncAttributeMaxDynamicSharedMemorySize, FLASH_SMEM_BYTES);

    uint32_t *xh, *xl, *wqh, *wql, *woh, *wol, *aoh, *aol;
    cudaGetSymbolAddress((void**)&xh,  g_xh);  cudaGetSymbolAddress((void**)&xl,  g_xl);
    cudaGetSymbolAddress((void**)&wqh, g_wqh); cudaGetSymbolAddress((void**)&wql, g_wql);
    cudaGetSymbolAddress((void**)&woh, g_woh); cudaGetSymbolAddress((void**)&wol, g_wol);
    cudaGetSymbolAddress((void**)&aoh, g_aoh); cudaGetSymbolAddress((void**)&aol, g_aol);

    // 0) pre-pack operands to hi/lo bf16 pairs
    prep_pack<<<(B_*S_*512 + 255) / 256, 256>>>(x,     xh,  xl,  B_*S_*512);
    prep_pack<<<(3*D_*512  + 255) / 256, 256>>>(w_qkv, wqh, wql, 3*D_*512);
    prep_pack<<<(D_*512    + 255) / 256, 256>>>(w_out, woh, wol, D_*512);

    // 1) QKV projection + fused RoPE + hi/lo split
    mm_ldsm<0><<<dim3(24, 64), 256, MM_SMEM_BYTES>>>(xh, xl, wqh, wql, nullptr);

    // 2) V transpose + hi/lo split
    v_convert<<<dim3(S_/64, H_, B_), 256>>>();

    // 3) Flash attention (BQ=128, cp.async pipelined)
    flash_mma<<<dim3(S_/128, H_, B_), 256, FLASH_SMEM_BYTES>>>();

    // 4) Output projection
    mm_ldsm<1><<<dim3(8, 64), 256, MM_SMEM_BYTES>>>(aoh, aol, woh, wol, out);
}

// round 10
// speedup vs baseline: 2.0392x; 1.0703x over previous
#include <cuda_runtime.h>
#include <cuda_bf16.h>
#include <cstdint>
#include <math.h>

#define B_  4
#define S_  2048
#define H_  16
#define DK_ 64
#define D_  1024

// Scratch (device globals — allocation-free rule)
__device__ float    g_v [B_*H_*S_*DK_];
__device__ uint32_t g_qh[B_*H_*S_*32];
__device__ uint32_t g_ql[B_*H_*S_*32];
__device__ uint32_t g_kh[B_*H_*S_*32];
__device__ uint32_t g_kl[B_*H_*S_*32];
__device__ uint32_t g_vh[B_*H_*DK_*(S_/2)];
__device__ uint32_t g_vl[B_*H_*DK_*(S_/2)];
__device__ uint32_t g_xh [B_*S_*512];
__device__ uint32_t g_xl [B_*S_*512];
__device__ uint32_t g_wqh[3*D_*512];
__device__ uint32_t g_wql[3*D_*512];
__device__ uint32_t g_woh[D_*512];
__device__ uint32_t g_wol[D_*512];
__device__ uint32_t g_aoh[B_*S_*512];
__device__ uint32_t g_aol[B_*S_*512];

// ======================= helpers ===========================================
__device__ __forceinline__ void mma_bf16(float* c,
                                         uint32_t a0, uint32_t a1, uint32_t a2, uint32_t a3,
                                         uint32_t b0, uint32_t b1) {
    asm volatile(
        "mma.sync.aligned.m16n8k16.row.col.f32.bf16.bf16.f32 "
        "{%0,%1,%2,%3}, {%4,%5,%6,%7}, {%8,%9}, {%0,%1,%2,%3};"
        : "+f"(c[0]), "+f"(c[1]), "+f"(c[2]), "+f"(c[3])
        : "r"(a0), "r"(a1), "r"(a2), "r"(a3), "r"(b0), "r"(b1));
}

__device__ __forceinline__ void cvt_hilo(float x, float y, uint32_t& hi, uint32_t& lo) {
    __nv_bfloat162 h = __floats2bfloat162_rn(x, y);
    float hx = __bfloat162float(h.x);
    float hy = __bfloat162float(h.y);
    __nv_bfloat162 l = __floats2bfloat162_rn(x - hx, y - hy);
    hi = *(uint32_t*)&h;
    lo = *(uint32_t*)&l;
}

__device__ __forceinline__ uint32_t smem_to_u32(const void* p) {
    uint32_t a;
    asm("{ .reg .u64 t; cvta.to.shared.u64 t, %1; cvt.u32.u64 %0, t; }"
        : "=r"(a) : "l"(p));
    return a;
}
__device__ __forceinline__ void cp_async16(uint32_t dst_smem, const void* src) {
    asm volatile("cp.async.cg.shared.global [%0], [%1], 16;"
                 :: "r"(dst_smem), "l"(src) : "memory");
}
__device__ __forceinline__ void cp_commit() {
    asm volatile("cp.async.commit_group;" ::: "memory");
}
template<int N>
__device__ __forceinline__ void cp_wait() {
    asm volatile("cp.async.wait_group %0;" :: "n"(N) : "memory");
}
__device__ __forceinline__ void ldsm_x4(uint32_t& r0, uint32_t& r1, uint32_t& r2,
                                        uint32_t& r3, uint32_t addr) {
    asm volatile("ldmatrix.sync.aligned.m8n8.x4.shared.b16 {%0,%1,%2,%3}, [%4];"
                 : "=r"(r0), "=r"(r1), "=r"(r2), "=r"(r3) : "r"(addr));
}
// soft cap: 50*tanh(s*0.125/50) = 50 - 100/(exp(s*0.005)+1)
__device__ __forceinline__ float softcap(float s) {
    float e = __expf(s * 0.005f);
    return 50.f - __fdividef(100.f, e + 1.f);
}

// ---------------------------------------------------------------------------
__global__ void prep_pack(const float* __restrict__ src, uint32_t* __restrict__ dh,
                          uint32_t* __restrict__ dl, int npairs) {
    int i = blockIdx.x * blockDim.x + threadIdx.x;
    if (i >= npairs) return;
    float2 v = ((const float2*)src)[i];
    uint32_t hh, ll;
    cvt_hilo(v.x, v.y, hh, ll);
    dh[i] = hh;
    dl[i] = ll;
}

// ---------------------------------------------------------------------------
// bf16x3 NT GEMM, pass-ordered MMA issue (same-acc distance 8).
// ---------------------------------------------------------------------------
#define PST 20
#define MMBUF (4 * 128 * PST)
#define MM_SMEM_BYTES (2 * MMBUF * 4)      // 81920

template<int MODE>
__global__ void __launch_bounds__(256, 2) mm_ldsm(const uint32_t* __restrict__ Ah_,
                                                  const uint32_t* __restrict__ Al_,
                                                  const uint32_t* __restrict__ Wh_,
                                                  const uint32_t* __restrict__ Wl_,
                                                  float* __restrict__ C) {
    extern __shared__ uint32_t smu[];
    const int tid = threadIdx.x;
    const int w = tid >> 5, l = tid & 31;
    const int wm = w & 3, wn = w >> 2;
    const int g = l >> 2, tq = l & 3;
    const int r8 = l & 7, seg = l >> 3;
    const int bm = blockIdx.y, bn = blockIdx.x;
    const uint32_t sb = smem_to_u32(smu);

    const uint32_t* srcs[4] = {
        Ah_ + (size_t)bm * 128 * 512, Al_ + (size_t)bm * 128 * 512,
        Wh_ + (size_t)bn * 128 * 512, Wl_ + (size_t)bn * 128 * 512 };

    const int crow = tid >> 1, cpp = (tid & 1) * 8;

    auto issue = [&](int c, int p) {
        uint32_t dst = sb + (uint32_t)((p * MMBUF + crow * PST + cpp) * 4);
#pragma unroll
        for (int m = 0; m < 4; m++) {
            const uint32_t* s = srcs[m] + (size_t)crow * 512 + c * 16 + cpp;
            cp_async16(dst + m * 128 * PST * 4, s);
            cp_async16(dst + m * 128 * PST * 4 + 16, s + 4);
        }
        cp_commit();
    };

    float acc[2][8][4];
#pragma unroll
    for (int mi = 0; mi < 2; mi++)
#pragma unroll
        for (int ni = 0; ni < 8; ni++)
#pragma unroll
            for (int r = 0; r < 4; r++) acc[mi][ni][r] = 0.f;

    uint32_t aoff[2], boff[4];
#pragma unroll
    for (int mi = 0; mi < 2; mi++)
        aoff[mi] = (uint32_t)((wm * 32 + mi * 16 + r8 + (seg & 1) * 8) * PST + (seg >> 1) * 4);
#pragma unroll
    for (int nj = 0; nj < 4; nj++)
        boff[nj] = (uint32_t)(2 * 128 * PST +
                              (wn * 64 + nj * 16 + r8 + (seg >> 1) * 8) * PST + (seg & 1) * 4);

    issue(0, 0);
    issue(1, 1);

    for (int c = 0; c < 32; c++) {
        const int p = c & 1;
        cp_wait<1>();
        __syncthreads();
        const uint32_t base = sb + (uint32_t)(p * MMBUF * 4);

#pragma unroll
        for (int ks = 0; ks < 2; ks++) {
            const uint32_t kcb = ks * 8 * 4;
            uint32_t ah[2][4], al[2][4];
#pragma unroll
            for (int mi = 0; mi < 2; mi++) {
                uint32_t ad = base + aoff[mi] * 4 + kcb;
                ldsm_x4(ah[mi][0], ah[mi][1], ah[mi][2], ah[mi][3], ad);
                ldsm_x4(al[mi][0], al[mi][1], al[mi][2], al[mi][3], ad + 128 * PST * 4);
            }
#pragma unroll
            for (int njp = 0; njp < 2; njp++) {
                uint32_t bh[2][4], bl[2][4];
#pragma unroll
                for (int j2 = 0; j2 < 2; j2++) {
                    uint32_t bd = base + boff[njp * 2 + j2] * 4 + kcb;
                    ldsm_x4(bh[j2][0], bh[j2][1], bh[j2][2], bh[j2][3], bd);
                    ldsm_x4(bl[j2][0], bl[j2][1], bl[j2][2], bl[j2][3], bd + 128 * PST * 4);
                }
                // pass 1: Ah x Bh  (8 independent accs)
#pragma unroll
                for (int j2 = 0; j2 < 2; j2++)
#pragma unroll
                    for (int hf = 0; hf < 2; hf++)
#pragma unroll
                        for (int mi = 0; mi < 2; mi++)
                            mma_bf16(acc[mi][(njp * 2 + j2) * 2 + hf],
                                     ah[mi][0], ah[mi][1], ah[mi][2], ah[mi][3],
                                     bh[j2][hf * 2], bh[j2][hf * 2 + 1]);
                // pass 2: Ah x Bl
#pragma unroll
                for (int j2 = 0; j2 < 2; j2++)
#pragma unroll
                    for (int hf = 0; hf < 2; hf++)
#pragma unroll
                        for (int mi = 0; mi < 2; mi++)
                            mma_bf16(acc[mi][(njp * 2 + j2) * 2 + hf],
                                     ah[mi][0], ah[mi][1], ah[mi][2], ah[mi][3],
                                     bl[j2][hf * 2], bl[j2][hf * 2 + 1]);
                // pass 3: Al x Bh
#pragma unroll
                for (int j2 = 0; j2 < 2; j2++)
#pragma unroll
                    for (int hf = 0; hf < 2; hf++)
#pragma unroll
                        for (int mi = 0; mi < 2; mi++)
                            mma_bf16(acc[mi][(njp * 2 + j2) * 2 + hf],
                                     al[mi][0], al[mi][1], al[mi][2], al[mi][3],
                                     bh[j2][hf * 2], bh[j2][hf * 2 + 1]);
            }
        }
        __syncthreads();
        if (c + 2 < 32) issue(c + 2, p);
    }

    const int row0 = wm * 32, col0 = wn * 64;
#pragma unroll
    for (int mi = 0; mi < 2; mi++) {
#pragma unroll
        for (int half = 0; half < 2; half++) {
            int r = bm * 128 + row0 + mi * 16 + g + half * 8;
#pragma unroll
            for (int ni = 0; ni < 8; ni++) {
                int cb = bn * 128 + col0 + ni * 8 + 2 * tq;
                float2 val = make_float2(acc[mi][ni][half * 2 + 0],
                                         acc[mi][ni][half * 2 + 1]);
                if (MODE == 0) {
                    int which = cb >> 10;
                    int h  = (cb >> 6) & 15;
                    int d0 = cb & 63;
                    int b  = r >> 11;
                    int s  = r & 2047;
                    if (which == 2) {
                        *(float2*)(g_v + (((size_t)(b * H_ + h) * S_ + s) * DK_ + d0)) = val;
                    } else {
                        int pr = d0 >> 1;
                        float invf = exp2f(-(float)pr * (13.28771237954945f / 32.0f));
                        float ang = (float)s * invf;
                        float sn, cs;
                        sincosf(ang, &sn, &cs);
                        float ev = val.x * cs - val.y * sn;
                        float od = val.x * sn + val.y * cs;
                        uint32_t hh, ll;
                        cvt_hilo(ev, od, hh, ll);
                        size_t idx = ((size_t)(b * H_ + h) * S_ + s) * 32 + pr;
                        if (which == 0) { g_qh[idx] = hh; g_ql[idx] = ll; }
                        else            { g_kh[idx] = hh; g_kl[idx] = ll; }
                    }
                } else {
                    *(float2*)(C + (size_t)r * D_ + cb) = val;
                }
            }
        }
    }
}

// ---------------------------------------------------------------------------
__global__ void __launch_bounds__(256) v_convert() {
    __shared__ float ts[64 * 65];
    const int tid = threadIdx.x;
    const int kt = blockIdx.x, h = blockIdx.y, b = blockIdx.z;
    const int bh = b * H_ + h;

    const float* src = g_v + ((size_t)bh * S_ + kt * 64) * DK_;
#pragma unroll
    for (int i = 0; i < 4; i++) {
        int f = tid + i * 256;
        int row = f >> 4, c4 = (f & 15) * 4;
        float4 v = *(const float4*)(src + row * DK_ + c4);
        ts[row * 65 + c4 + 0] = v.x;
        ts[row * 65 + c4 + 1] = v.y;
        ts[row * 65 + c4 + 2] = v.z;
        ts[row * 65 + c4 + 3] = v.w;
    }
    __syncthreads();

    const int w = tid >> 5, p = tid & 31;
#pragma unroll
    for (int i = 0; i < 8; i++) {
        int c = w * 8 + i;
        float x1 = ts[(2 * p) * 65 + c];
        float x2 = ts[(2 * p + 1) * 65 + c];
        uint32_t hh, ll;
        cvt_hilo(x1, x2, hh, ll);
        size_t o = ((size_t)bh * 64 + c) * (S_ / 2) + kt * 32 + p;
        g_vh[o] = hh;
        g_vl[o] = ll;
    }
}

// ---------------------------------------------------------------------------
// Flash attention: BQ=128, cp.async double-buffered KV, pass-ordered MMAs.
// ---------------------------------------------------------------------------
#define FST 36
#define FQW  (2 * 128 * FST)
#define FKVW (4 * 64 * FST)
#define FLASH_SMEM_BYTES ((FQW + 2 * FKVW) * 4)   // 110592

__global__ void __launch_bounds__(256, 2) flash_mma() {
    extern __shared__ uint32_t su[];
    uint32_t* Qh = su;
    uint32_t* Ql = su + 128 * FST;

    const int tid = threadIdx.x;
    const int w = tid >> 5, l = tid & 31;
    const int g = l >> 2, tq = l & 3;
    const int q0 = (int)(gridDim.x - 1 - blockIdx.x) * 128;
    const int h = blockIdx.y, b = blockIdx.z;
    const size_t bhp = (size_t)(b * H_ + h) * S_ * 32;
    const size_t bhv = (size_t)(b * H_ + h) * 64;
    const uint32_t sb = smem_to_u32(su);

    const int kvrow = tid >> 2;
    const int kvq   = (tid & 3) * 8;

    auto issue_kv = [&](int kt, int s) {
        uint32_t base = sb + (uint32_t)((FQW + s * FKVW + kvrow * FST + kvq) * 4);
        const uint32_t* k_h = g_kh + bhp + (size_t)(kt * 64 + kvrow) * 32 + kvq;
        const uint32_t* k_l = g_kl + bhp + (size_t)(kt * 64 + kvrow) * 32 + kvq;
        const uint32_t* v_h = g_vh + (bhv + kvrow) * (S_ / 2) + kt * 32 + kvq;
        const uint32_t* v_l = g_vl + (bhv + kvrow) * (S_ / 2) + kt * 32 + kvq;
        cp_async16(base,                      k_h);
        cp_async16(base + 16,                 k_h + 4);
        cp_async16(base + 64*FST*4,           k_l);
        cp_async16(base + 64*FST*4 + 16,      k_l + 4);
        cp_async16(base + 2*64*FST*4,         v_h);
        cp_async16(base + 2*64*FST*4 + 16,    v_h + 4);
        cp_async16(base + 3*64*FST*4,         v_l);
        cp_async16(base + 3*64*FST*4 + 16,    v_l + 4);
        cp_commit();
    };

    issue_kv(0, 0);
    {
        int row = tid >> 1, pb = (tid & 1) * 16;
        const uint32_t* sh = g_qh + bhp + (size_t)(q0 + row) * 32 + pb;
        const uint32_t* sl = g_ql + bhp + (size_t)(q0 + row) * 32 + pb;
        uint32_t d = sb + (uint32_t)((row * FST + pb) * 4);
#pragma unroll
        for (int j = 0; j < 4; j++) {
            cp_async16(d + j * 16,                 sh + j * 4);
            cp_async16(d + 128*FST*4 + j * 16,     sl + j * 4);
        }
        cp_commit();
    }
    cp_wait<0>();
    __syncthreads();

    uint32_t qh[4][4], ql[4][4];
#pragma unroll
    for (int kk = 0; kk < 4; kk++) {
        int ra = (w * 16 + g) * FST + kk * 8 + tq;
        int rb = ra + 8 * FST;
        qh[kk][0] = Qh[ra];     qh[kk][1] = Qh[rb];
        qh[kk][2] = Qh[ra + 4]; qh[kk][3] = Qh[rb + 4];
        ql[kk][0] = Ql[ra];     ql[kk][1] = Ql[rb];
        ql[kk][2] = Ql[ra + 4]; ql[kk][3] = Ql[rb + 4];
    }

    float m0 = -INFINITY, m1 = -INFINITY, l0s = 0.f, l1s = 0.f;
    float o[8][4];
#pragma unroll
    for (int ni = 0; ni < 8; ni++)
#pragma unroll
        for (int r = 0; r < 4; r++) o[ni][r] = 0.f;

    const int ig0 = q0 + w * 16 + g;
    const int ig1 = ig0 + 8;
    const int rowmax = q0 + w * 16 + 15;
    const int nkt = (q0 + 127) >> 6;

    for (int kt = 0; kt <= nkt; kt++) {
        const int p = kt & 1;
        if (kt > 0) cp_wait<0>();
        __syncthreads();
        if (kt < nkt) issue_kv(kt + 1, p ^ 1);

        if (kt * 64 <= rowmax) {
            uint32_t* Kh_ = su + FQW + p * FKVW;
            uint32_t* Kl_ = Kh_ + 64 * FST;
            uint32_t* Vh_ = Kh_ + 2 * 64 * FST;
            uint32_t* Vl_ = Kh_ + 3 * 64 * FST;

            // S = Q K^T: groups of 4 ni, pass-ordered (same-acc distance 4)
            float sc[8][4];
#pragma unroll
            for (int ni = 0; ni < 8; ni++)
#pragma unroll
                for (int r = 0; r < 4; r++) sc[ni][r] = 0.f;
#pragma unroll
            for (int kk = 0; kk < 4; kk++) {
#pragma unroll
                for (int nig = 0; nig < 2; nig++) {
                    uint32_t kh4[4][2], kl4[4][2];
#pragma unroll
                    for (int j = 0; j < 4; j++) {
                        int rn = ((nig * 4 + j) * 8 + g) * FST + kk * 8 + tq;
                        kh4[j][0] = Kh_[rn]; kh4[j][1] = Kh_[rn + 4];
                        kl4[j][0] = Kl_[rn]; kl4[j][1] = Kl_[rn + 4];
                    }
#pragma unroll
                    for (int j = 0; j < 4; j++)
                        mma_bf16(sc[nig * 4 + j], qh[kk][0], qh[kk][1], qh[kk][2], qh[kk][3],
                                 kh4[j][0], kh4[j][1]);
#pragma unroll
                    for (int j = 0; j < 4; j++)
                        mma_bf16(sc[nig * 4 + j], qh[kk][0], qh[kk][1], qh[kk][2], qh[kk][3],
                                 kl4[j][0], kl4[j][1]);
#pragma unroll
                    for (int j = 0; j < 4; j++)
                        mma_bf16(sc[nig * 4 + j], ql[kk][0], ql[kk][1], ql[kk][2], ql[kk][3],
                                 kh4[j][0], kh4[j][1]);
                }
            }

            // scale + softcap (fast) + causal mask
            const bool diag = (kt * 64 + 63) > ig0;
#pragma unroll
            for (int ni = 0; ni < 8; ni++) {
                int jg = kt * 64 + ni * 8 + 2 * tq;
#pragma unroll
                for (int r = 0; r < 4; r++) {
                    float v = softcap(sc[ni][r]);
                    if (diag) {
                        int col = jg + (r & 1);
                        int row = (r < 2) ? ig0 : ig1;
                        if (col > row) v = -1e30f;
                    }
                    sc[ni][r] = v;
                }
            }

            // online softmax
            float mx0 = -INFINITY, mx1 = -INFINITY;
#pragma unroll
            for (int ni = 0; ni < 8; ni++) {
                mx0 = fmaxf(mx0, fmaxf(sc[ni][0], sc[ni][1]));
                mx1 = fmaxf(mx1, fmaxf(sc[ni][2], sc[ni][3]));
            }
            mx0 = fmaxf(mx0, __shfl_xor_sync(0xffffffffu, mx0, 1));
            mx0 = fmaxf(mx0, __shfl_xor_sync(0xffffffffu, mx0, 2));
            mx1 = fmaxf(mx1, __shfl_xor_sync(0xffffffffu, mx1, 1));
            mx1 = fmaxf(mx1, __shfl_xor_sync(0xffffffffu, mx1, 2));
            float mn0 = fmaxf(m0, mx0), mn1 = fmaxf(m1, mx1);
            float s0 = 0.f, s1 = 0.f;
#pragma unroll
            for (int ni = 0; ni < 8; ni++) {
                sc[ni][0] = __expf(sc[ni][0] - mn0);
                sc[ni][1] = __expf(sc[ni][1] - mn0);
                sc[ni][2] = __expf(sc[ni][2] - mn1);
                sc[ni][3] = __expf(sc[ni][3] - mn1);
                s0 += sc[ni][0] + sc[ni][1];
                s1 += sc[ni][2] + sc[ni][3];
            }
            s0 += __shfl_xor_sync(0xffffffffu, s0, 1);
            s0 += __shfl_xor_sync(0xffffffffu, s0, 2);
            s1 += __shfl_xor_sync(0xffffffffu, s1, 1);
            s1 += __shfl_xor_sync(0xffffffffu, s1, 2);
            float c0 = __expf(m0 - mn0), c1 = __expf(m1 - mn1);
            l0s = l0s * c0 + s0; l1s = l1s * c1 + s1;
            m0 = mn0; m1 = mn1;
#pragma unroll
            for (int ni = 0; ni < 8; ni++) {
                o[ni][0] *= c0; o[ni][1] *= c0;
                o[ni][2] *= c1; o[ni][3] *= c1;
            }

            uint32_t ph[4][4], pl[4][4];
#pragma unroll
            for (int kk = 0; kk < 4; kk++) {
                int n0 = 2 * kk, n1 = 2 * kk + 1;
                cvt_hilo(sc[n0][0], sc[n0][1], ph[kk][0], pl[kk][0]);
                cvt_hilo(sc[n0][2], sc[n0][3], ph[kk][1], pl[kk][1]);
                cvt_hilo(sc[n1][0], sc[n1][1], ph[kk][2], pl[kk][2]);
                cvt_hilo(sc[n1][2], sc[n1][3], ph[kk][3], pl[kk][3]);
            }

            // O += P V: groups of 4 ni, pass-ordered
#pragma unroll
            for (int kk = 0; kk < 4; kk++) {
#pragma unroll
                for (int nig = 0; nig < 2; nig++) {
                    uint32_t vh4[4][2], vl4[4][2];
#pragma unroll
                    for (int j = 0; j < 4; j++) {
                        int rn = ((nig * 4 + j) * 8 + g) * FST + kk * 8 + tq;
                        vh4[j][0] = Vh_[rn]; vh4[j][1] = Vh_[rn + 4];
                        vl4[j][0] = Vl_[rn]; vl4[j][1] = Vl_[rn + 4];
                    }
#pragma unroll
                    for (int j = 0; j < 4; j++)
                        mma_bf16(o[nig * 4 + j], ph[kk][0], ph[kk][1], ph[kk][2], ph[kk][3],
                                 vh4[j][0], vh4[j][1]);
#pragma unroll
                    for (int j = 0; j < 4; j++)
                        mma_bf16(o[nig * 4 + j], ph[kk][0], ph[kk][1], ph[kk][2], ph[kk][3],
                                 vl4[j][0], vl4[j][1]);
#pragma unroll
                    for (int j = 0; j < 4; j++)
                        mma_bf16(o[nig * 4 + j], pl[kk][0], pl[kk][1], pl[kk][2], pl[kk][3],
                                 vh4[j][0], vh4[j][1]);
                }
            }
        }
    }

    float inv0 = 1.0f / l0s, inv1 = 1.0f / l1s;
    size_t r0b = (size_t)(b * S_ + ig0) * 512 + h * 32;
    size_t r1b = (size_t)(b * S_ + ig1) * 512 + h * 32;
#pragma unroll
    for (int ni = 0; ni < 8; ni++) {
        int pr = ni * 4 + tq;
        uint32_t hh, ll;
        cvt_hilo(o[ni][0] * inv0, o[ni][1] * inv0, hh, ll);
        g_aoh[r0b + pr] = hh; g_aol[r0b + pr] = ll;
        cvt_hilo(o[ni][2] * inv1, o[ni][3] * inv1, hh, ll);
        g_aoh[r1b + pr] = hh; g_aol[r1b + pr] = ll;
    }
}

// ---------------------------------------------------------------------------
extern "C" void kernel_launch(void* const* d_in, const int* in_sizes, int n_in,
                              void* d_out, int out_size) {
    const float* x     = (const float*)d_in[0];
    const float* w_qkv = (const float*)d_in[1];
    const float* w_out = (const float*)d_in[2];
    float* out = (float*)d_out;

    cudaFuncSetAttribute(mm_ldsm<0>, cudaFuncAttributeMaxDynamicSharedMemorySize, MM_SMEM_BYTES);
    cudaFuncSetAttribute(mm_ldsm<1>, cudaFuncAttributeMaxDynamicSharedMemorySize, MM_SMEM_BYTES);
    cudaFuncSetAttribute(flash_mma,  cudaFuncAttributeMaxDynamicSharedMemorySize, FLASH_SMEM_BYTES);

    uint32_t *xh, *xl, *wqh, *wql, *woh, *wol, *aoh, *aol;
    cudaGetSymbolAddress((void**)&xh,  g_xh);  cudaGetSymbolAddress((void**)&xl,  g_xl);
    cudaGetSymbolAddress((void**)&wqh, g_wqh); cudaGetSymbolAddress((void**)&wql, g_wql);
    cudaGetSymbolAddress((void**)&woh, g_woh); cudaGetSymbolAddress((void**)&wol, g_wol);
    cudaGetSymbolAddress((void**)&aoh, g_aoh); cudaGetSymbolAddress((void**)&aol, g_aol);

    prep_pack<<<(B_*S_*512 + 255) / 256, 256>>>(x,     xh,  xl,  B_*S_*512);
    prep_pack<<<(3*D_*512  + 255) / 256, 256>>>(w_qkv, wqh, wql, 3*D_*512);
    prep_pack<<<(D_*512    + 255) / 256, 256>>>(w_out, woh, wol, D_*512);

    mm_ldsm<0><<<dim3(24, 64), 256, MM_SMEM_BYTES>>>(xh, xl, wqh, wql, nullptr);
    v_convert<<<dim3(S_/64, H_, B_), 256>>>();
    flash_mma<<<dim3(S_/128, H_, B_), 256, FLASH_SMEM_BYTES>>>();
    mm_ldsm<1><<<dim3(8, 64), 256, MM_SMEM_BYTES>>>(aoh, aol, woh, wol, out);
}

// round 11
// speedup vs baseline: 2.1225x; 1.0409x over previous
#include <cuda_runtime.h>
#include <cuda_bf16.h>
#include <cstdint>
#include <math.h>

#define B_  4
#define S_  2048
#define H_  16
#define DK_ 64
#define D_  1024

// Scratch (device globals — allocation-free rule)
__device__ float    g_v [B_*H_*S_*DK_];
__device__ uint32_t g_qh[B_*H_*S_*32];
__device__ uint32_t g_ql[B_*H_*S_*32];
__device__ uint32_t g_kh[B_*H_*S_*32];
__device__ uint32_t g_kl[B_*H_*S_*32];
__device__ uint32_t g_vh[B_*H_*DK_*(S_/2)];
__device__ uint32_t g_vl[B_*H_*DK_*(S_/2)];
__device__ uint32_t g_xh [B_*S_*512];
__device__ uint32_t g_xl [B_*S_*512];
__device__ uint32_t g_wqh[3*D_*512];
__device__ uint32_t g_wql[3*D_*512];
__device__ uint32_t g_woh[D_*512];
__device__ uint32_t g_wol[D_*512];
__device__ uint32_t g_aoh[B_*S_*512];
__device__ uint32_t g_aol[B_*S_*512];

// ======================= helpers ===========================================
__device__ __forceinline__ void mma_bf16(float* c,
                                         uint32_t a0, uint32_t a1, uint32_t a2, uint32_t a3,
                                         uint32_t b0, uint32_t b1) {
    asm volatile(
        "mma.sync.aligned.m16n8k16.row.col.f32.bf16.bf16.f32 "
        "{%0,%1,%2,%3}, {%4,%5,%6,%7}, {%8,%9}, {%0,%1,%2,%3};"
        : "+f"(c[0]), "+f"(c[1]), "+f"(c[2]), "+f"(c[3])
        : "r"(a0), "r"(a1), "r"(a2), "r"(a3), "r"(b0), "r"(b1));
}

__device__ __forceinline__ void cvt_hilo(float x, float y, uint32_t& hi, uint32_t& lo) {
    __nv_bfloat162 h = __floats2bfloat162_rn(x, y);
    float hx = __bfloat162float(h.x);
    float hy = __bfloat162float(h.y);
    __nv_bfloat162 l = __floats2bfloat162_rn(x - hx, y - hy);
    hi = *(uint32_t*)&h;
    lo = *(uint32_t*)&l;
}

__device__ __forceinline__ uint32_t smem_to_u32(const void* p) {
    uint32_t a;
    asm("{ .reg .u64 t; cvta.to.shared.u64 t, %1; cvt.u32.u64 %0, t; }"
        : "=r"(a) : "l"(p));
    return a;
}
__device__ __forceinline__ void cp_async16(uint32_t dst_smem, const void* src) {
    asm volatile("cp.async.cg.shared.global [%0], [%1], 16;"
                 :: "r"(dst_smem), "l"(src) : "memory");
}
__device__ __forceinline__ void cp_commit() {
    asm volatile("cp.async.commit_group;" ::: "memory");
}
template<int N>
__device__ __forceinline__ void cp_wait() {
    asm volatile("cp.async.wait_group %0;" :: "n"(N) : "memory");
}
__device__ __forceinline__ void ldsm_x4(uint32_t& r0, uint32_t& r1, uint32_t& r2,
                                        uint32_t& r3, uint32_t addr) {
    asm volatile("ldmatrix.sync.aligned.m8n8.x4.shared.b16 {%0,%1,%2,%3}, [%4];"
                 : "=r"(r0), "=r"(r1), "=r"(r2), "=r"(r3) : "r"(addr));
}
// soft cap: 50*tanh(s*0.125/50) = 50 - 100/(exp(s*0.005)+1)
__device__ __forceinline__ float softcap(float s) {
    float e = __expf(s * 0.005f);
    return 50.f - __fdividef(100.f, e + 1.f);
}

// ---------------------------------------------------------------------------
__global__ void prep_pack(const float* __restrict__ src, uint32_t* __restrict__ dh,
                          uint32_t* __restrict__ dl, int npairs) {
    int i = blockIdx.x * blockDim.x + threadIdx.x;
    if (i >= npairs) return;
    float2 v = ((const float2*)src)[i];
    uint32_t hh, ll;
    cvt_hilo(v.x, v.y, hh, ll);
    dh[i] = hh;
    dl[i] = ll;
}

// ---------------------------------------------------------------------------
// bf16x3 NT GEMM, single-sync double-buffered mainloop.
// ---------------------------------------------------------------------------
#define PST 20
#define MMBUF (4 * 128 * PST)
#define MM_SMEM_BYTES (2 * MMBUF * 4)      // 81920

template<int MODE>
__global__ void __launch_bounds__(256, 2) mm_ldsm(const uint32_t* __restrict__ Ah_,
                                                  const uint32_t* __restrict__ Al_,
                                                  const uint32_t* __restrict__ Wh_,
                                                  const uint32_t* __restrict__ Wl_,
                                                  float* __restrict__ C) {
    extern __shared__ uint32_t smu[];
    const int tid = threadIdx.x;
    const int w = tid >> 5, l = tid & 31;
    const int wm = w & 3, wn = w >> 2;
    const int g = l >> 2, tq = l & 3;
    const int r8 = l & 7, seg = l >> 3;
    const int bm = blockIdx.y, bn = blockIdx.x;
    const uint32_t sb = smem_to_u32(smu);

    const uint32_t* srcs[4] = {
        Ah_ + (size_t)bm * 128 * 512, Al_ + (size_t)bm * 128 * 512,
        Wh_ + (size_t)bn * 128 * 512, Wl_ + (size_t)bn * 128 * 512 };

    const int crow = tid >> 1, cpp = (tid & 1) * 8;

    auto issue = [&](int c, int p) {
        uint32_t dst = sb + (uint32_t)((p * MMBUF + crow * PST + cpp) * 4);
#pragma unroll
        for (int m = 0; m < 4; m++) {
            const uint32_t* s = srcs[m] + (size_t)crow * 512 + c * 16 + cpp;
            cp_async16(dst + m * 128 * PST * 4, s);
            cp_async16(dst + m * 128 * PST * 4 + 16, s + 4);
        }
        cp_commit();
    };

    float acc[2][8][4];
#pragma unroll
    for (int mi = 0; mi < 2; mi++)
#pragma unroll
        for (int ni = 0; ni < 8; ni++)
#pragma unroll
            for (int r = 0; r < 4; r++) acc[mi][ni][r] = 0.f;

    uint32_t aoff[2], boff[4];
#pragma unroll
    for (int mi = 0; mi < 2; mi++)
        aoff[mi] = (uint32_t)((wm * 32 + mi * 16 + r8 + (seg & 1) * 8) * PST + (seg >> 1) * 4);
#pragma unroll
    for (int nj = 0; nj < 4; nj++)
        boff[nj] = (uint32_t)(2 * 128 * PST +
                              (wn * 64 + nj * 16 + r8 + (seg >> 1) * 8) * PST + (seg & 1) * 4);

    issue(0, 0);

    for (int c = 0; c < 32; c++) {
        const int p = c & 1;
        cp_wait<0>();
        __syncthreads();                     // all warps done with slot p (iter c-1 compute)
        if (c + 1 < 32) issue(c + 1, p ^ 1); // overlaps compute below
        const uint32_t base = sb + (uint32_t)(p * MMBUF * 4);

#pragma unroll
        for (int ks = 0; ks < 2; ks++) {
            const uint32_t kcb = ks * 8 * 4;
            uint32_t ah[2][4], al[2][4];
#pragma unroll
            for (int mi = 0; mi < 2; mi++) {
                uint32_t ad = base + aoff[mi] * 4 + kcb;
                ldsm_x4(ah[mi][0], ah[mi][1], ah[mi][2], ah[mi][3], ad);
                ldsm_x4(al[mi][0], al[mi][1], al[mi][2], al[mi][3], ad + 128 * PST * 4);
            }
#pragma unroll
            for (int njp = 0; njp < 2; njp++) {
                uint32_t bh[2][4], bl[2][4];
#pragma unroll
                for (int j2 = 0; j2 < 2; j2++) {
                    uint32_t bd = base + boff[njp * 2 + j2] * 4 + kcb;
                    ldsm_x4(bh[j2][0], bh[j2][1], bh[j2][2], bh[j2][3], bd);
                    ldsm_x4(bl[j2][0], bl[j2][1], bl[j2][2], bl[j2][3], bd + 128 * PST * 4);
                }
#pragma unroll
                for (int j2 = 0; j2 < 2; j2++)
#pragma unroll
                    for (int hf = 0; hf < 2; hf++)
#pragma unroll
                        for (int mi = 0; mi < 2; mi++)
                            mma_bf16(acc[mi][(njp * 2 + j2) * 2 + hf],
                                     ah[mi][0], ah[mi][1], ah[mi][2], ah[mi][3],
                                     bh[j2][hf * 2], bh[j2][hf * 2 + 1]);
#pragma unroll
                for (int j2 = 0; j2 < 2; j2++)
#pragma unroll
                    for (int hf = 0; hf < 2; hf++)
#pragma unroll
                        for (int mi = 0; mi < 2; mi++)
                            mma_bf16(acc[mi][(njp * 2 + j2) * 2 + hf],
                                     ah[mi][0], ah[mi][1], ah[mi][2], ah[mi][3],
                                     bl[j2][hf * 2], bl[j2][hf * 2 + 1]);
#pragma unroll
                for (int j2 = 0; j2 < 2; j2++)
#pragma unroll
                    for (int hf = 0; hf < 2; hf++)
#pragma unroll
                        for (int mi = 0; mi < 2; mi++)
                            mma_bf16(acc[mi][(njp * 2 + j2) * 2 + hf],
                                     al[mi][0], al[mi][1], al[mi][2], al[mi][3],
                                     bh[j2][hf * 2], bh[j2][hf * 2 + 1]);
            }
        }
    }

    const int row0 = wm * 32, col0 = wn * 64;
#pragma unroll
    for (int mi = 0; mi < 2; mi++) {
#pragma unroll
        for (int half = 0; half < 2; half++) {
            int r = bm * 128 + row0 + mi * 16 + g + half * 8;
#pragma unroll
            for (int ni = 0; ni < 8; ni++) {
                int cb = bn * 128 + col0 + ni * 8 + 2 * tq;
                float2 val = make_float2(acc[mi][ni][half * 2 + 0],
                                         acc[mi][ni][half * 2 + 1]);
                if (MODE == 0) {
                    int which = cb >> 10;
                    int h  = (cb >> 6) & 15;
                    int d0 = cb & 63;
                    int b  = r >> 11;
                    int s  = r & 2047;
                    if (which == 2) {
                        *(float2*)(g_v + (((size_t)(b * H_ + h) * S_ + s) * DK_ + d0)) = val;
                    } else {
                        int pr = d0 >> 1;
                        float invf = exp2f(-(float)pr * (13.28771237954945f / 32.0f));
                        float ang = (float)s * invf;
                        float sn, cs;
                        sincosf(ang, &sn, &cs);
                        float ev = val.x * cs - val.y * sn;
                        float od = val.x * sn + val.y * cs;
                        uint32_t hh, ll;
                        cvt_hilo(ev, od, hh, ll);
                        size_t idx = ((size_t)(b * H_ + h) * S_ + s) * 32 + pr;
                        if (which == 0) { g_qh[idx] = hh; g_ql[idx] = ll; }
                        else            { g_kh[idx] = hh; g_kl[idx] = ll; }
                    }
                } else {
                    *(float2*)(C + (size_t)r * D_ + cb) = val;
                }
            }
        }
    }
}

// ---------------------------------------------------------------------------
__global__ void __launch_bounds__(256) v_convert() {
    __shared__ float ts[64 * 65];
    const int tid = threadIdx.x;
    const int kt = blockIdx.x, h = blockIdx.y, b = blockIdx.z;
    const int bh = b * H_ + h;

    const float* src = g_v + ((size_t)bh * S_ + kt * 64) * DK_;
#pragma unroll
    for (int i = 0; i < 4; i++) {
        int f = tid + i * 256;
        int row = f >> 4, c4 = (f & 15) * 4;
        float4 v = *(const float4*)(src + row * DK_ + c4);
        ts[row * 65 + c4 + 0] = v.x;
        ts[row * 65 + c4 + 1] = v.y;
        ts[row * 65 + c4 + 2] = v.z;
        ts[row * 65 + c4 + 3] = v.w;
    }
    __syncthreads();

    const int w = tid >> 5, p = tid & 31;
#pragma unroll
    for (int i = 0; i < 8; i++) {
        int c = w * 8 + i;
        float x1 = ts[(2 * p) * 65 + c];
        float x2 = ts[(2 * p + 1) * 65 + c];
        uint32_t hh, ll;
        cvt_hilo(x1, x2, hh, ll);
        size_t o = ((size_t)bh * 64 + c) * (S_ / 2) + kt * 32 + p;
        g_vh[o] = hh;
        g_vl[o] = ll;
    }
}

// ---------------------------------------------------------------------------
// Flash attention: BQ=128, cp.async double-buffered KV, ldmatrix K/V frags.
// ---------------------------------------------------------------------------
#define FST 36
#define FQW  (2 * 128 * FST)
#define FKVW (4 * 64 * FST)
#define FLASH_SMEM_BYTES ((FQW + 2 * FKVW) * 4)   // 110592

__global__ void __launch_bounds__(256, 2) flash_mma() {
    extern __shared__ uint32_t su[];
    uint32_t* Qh = su;
    uint32_t* Ql = su + 128 * FST;

    const int tid = threadIdx.x;
    const int w = tid >> 5, l = tid & 31;
    const int g = l >> 2, tq = l & 3;
    const int r8 = l & 7, seg = l >> 3;
    const int q0 = (int)(gridDim.x - 1 - blockIdx.x) * 128;
    const int h = blockIdx.y, b = blockIdx.z;
    const size_t bhp = (size_t)(b * H_ + h) * S_ * 32;
    const size_t bhv = (size_t)(b * H_ + h) * 64;
    const uint32_t sb = smem_to_u32(su);

    const int kvrow = tid >> 2;
    const int kvq   = (tid & 3) * 8;

    auto issue_kv = [&](int kt, int s) {
        uint32_t base = sb + (uint32_t)((FQW + s * FKVW + kvrow * FST + kvq) * 4);
        const uint32_t* k_h = g_kh + bhp + (size_t)(kt * 64 + kvrow) * 32 + kvq;
        const uint32_t* k_l = g_kl + bhp + (size_t)(kt * 64 + kvrow) * 32 + kvq;
        const uint32_t* v_h = g_vh + (bhv + kvrow) * (S_ / 2) + kt * 32 + kvq;
        const uint32_t* v_l = g_vl + (bhv + kvrow) * (S_ / 2) + kt * 32 + kvq;
        cp_async16(base,                      k_h);
        cp_async16(base + 16,                 k_h + 4);
        cp_async16(base + 64*FST*4,           k_l);
        cp_async16(base + 64*FST*4 + 16,      k_l + 4);
        cp_async16(base + 2*64*FST*4,         v_h);
        cp_async16(base + 2*64*FST*4 + 16,    v_h + 4);
        cp_async16(base + 3*64*FST*4,         v_l);
        cp_async16(base + 3*64*FST*4 + 16,    v_l + 4);
        cp_commit();
    };

    issue_kv(0, 0);
    {
        int row = tid >> 1, pb = (tid & 1) * 16;
        const uint32_t* sh = g_qh + bhp + (size_t)(q0 + row) * 32 + pb;
        const uint32_t* sl = g_ql + bhp + (size_t)(q0 + row) * 32 + pb;
        uint32_t d = sb + (uint32_t)((row * FST + pb) * 4);
#pragma unroll
        for (int j = 0; j < 4; j++) {
            cp_async16(d + j * 16,                 sh + j * 4);
            cp_async16(d + 128*FST*4 + j * 16,     sl + j * 4);
        }
        cp_commit();
    }
    cp_wait<0>();
    __syncthreads();

    uint32_t qh[4][4], ql[4][4];
#pragma unroll
    for (int kk = 0; kk < 4; kk++) {
        int ra = (w * 16 + g) * FST + kk * 8 + tq;
        int rb = ra + 8 * FST;
        qh[kk][0] = Qh[ra];     qh[kk][1] = Qh[rb];
        qh[kk][2] = Qh[ra + 4]; qh[kk][3] = Qh[rb + 4];
        ql[kk][0] = Ql[ra];     ql[kk][1] = Ql[rb];
        ql[kk][2] = Ql[ra + 4]; ql[kk][3] = Ql[rb + 4];
    }

    // per-lane ldmatrix B-fragment offsets (words): nj covers ni=2nj,2nj+1
    uint32_t fboff[4];
#pragma unroll
    for (int nj = 0; nj < 4; nj++)
        fboff[nj] = (uint32_t)((nj * 16 + r8 + (seg >> 1) * 8) * FST + (seg & 1) * 4);

    float m0 = -INFINITY, m1 = -INFINITY, l0s = 0.f, l1s = 0.f;
    float o[8][4];
#pragma unroll
    for (int ni = 0; ni < 8; ni++)
#pragma unroll
        for (int r = 0; r < 4; r++) o[ni][r] = 0.f;

    const int ig0 = q0 + w * 16 + g;
    const int ig1 = ig0 + 8;
    const int rowmax = q0 + w * 16 + 15;
    const int nkt = (q0 + 127) >> 6;

    for (int kt = 0; kt <= nkt; kt++) {
        const int p = kt & 1;
        if (kt > 0) cp_wait<0>();
        __syncthreads();
        if (kt < nkt) issue_kv(kt + 1, p ^ 1);

        if (kt * 64 <= rowmax) {
            const uint32_t kbase = sb + (uint32_t)((FQW + p * FKVW) * 4);
            const uint32_t vbase = kbase + 2 * 64 * FST * 4;

            // S = Q K^T, ldmatrix fragments, pass-ordered
            float sc[8][4];
#pragma unroll
            for (int ni = 0; ni < 8; ni++)
#pragma unroll
                for (int r = 0; r < 4; r++) sc[ni][r] = 0.f;
#pragma unroll
            for (int kk = 0; kk < 4; kk++) {
                const uint32_t kcb = kk * 8 * 4;
#pragma unroll
                for (int nig = 0; nig < 2; nig++) {
                    uint32_t bh[2][4], bl[2][4];
#pragma unroll
                    for (int j2 = 0; j2 < 2; j2++) {
                        uint32_t ad = kbase + fboff[nig * 2 + j2] * 4 + kcb;
                        ldsm_x4(bh[j2][0], bh[j2][1], bh[j2][2], bh[j2][3], ad);
                        ldsm_x4(bl[j2][0], bl[j2][1], bl[j2][2], bl[j2][3], ad + 64 * FST * 4);
                    }
#pragma unroll
                    for (int j2 = 0; j2 < 2; j2++)
#pragma unroll
                        for (int hf = 0; hf < 2; hf++)
                            mma_bf16(sc[nig * 4 + j2 * 2 + hf],
                                     qh[kk][0], qh[kk][1], qh[kk][2], qh[kk][3],
                                     bh[j2][hf * 2], bh[j2][hf * 2 + 1]);
#pragma unroll
                    for (int j2 = 0; j2 < 2; j2++)
#pragma unroll
                        for (int hf = 0; hf < 2; hf++)
                            mma_bf16(sc[nig * 4 + j2 * 2 + hf],
                                     qh[kk][0], qh[kk][1], qh[kk][2], qh[kk][3],
                                     bl[j2][hf * 2], bl[j2][hf * 2 + 1]);
#pragma unroll
                    for (int j2 = 0; j2 < 2; j2++)
#pragma unroll
                        for (int hf = 0; hf < 2; hf++)
                            mma_bf16(sc[nig * 4 + j2 * 2 + hf],
                                     ql[kk][0], ql[kk][1], ql[kk][2], ql[kk][3],
                                     bh[j2][hf * 2], bh[j2][hf * 2 + 1]);
                }
            }

            // scale + softcap (fast) + causal mask
            const bool diag = (kt * 64 + 63) > ig0;
#pragma unroll
            for (int ni = 0; ni < 8; ni++) {
                int jg = kt * 64 + ni * 8 + 2 * tq;
#pragma unroll
                for (int r = 0; r < 4; r++) {
                    float v = softcap(sc[ni][r]);
                    if (diag) {
                        int col = jg + (r & 1);
                        int row = (r < 2) ? ig0 : ig1;
                        if (col > row) v = -1e30f;
                    }
                    sc[ni][r] = v;
                }
            }

            // online softmax
            float mx0 = -INFINITY, mx1 = -INFINITY;
#pragma unroll
            for (int ni = 0; ni < 8; ni++) {
                mx0 = fmaxf(mx0, fmaxf(sc[ni][0], sc[ni][1]));
                mx1 = fmaxf(mx1, fmaxf(sc[ni][2], sc[ni][3]));
            }
            mx0 = fmaxf(mx0, __shfl_xor_sync(0xffffffffu, mx0, 1));
            mx0 = fmaxf(mx0, __shfl_xor_sync(0xffffffffu, mx0, 2));
            mx1 = fmaxf(mx1, __shfl_xor_sync(0xffffffffu, mx1, 1));
            mx1 = fmaxf(mx1, __shfl_xor_sync(0xffffffffu, mx1, 2));
            float mn0 = fmaxf(m0, mx0), mn1 = fmaxf(m1, mx1);
            float s0 = 0.f, s1 = 0.f;
#pragma unroll
            for (int ni = 0; ni < 8; ni++) {
                sc[ni][0] = __expf(sc[ni][0] - mn0);
                sc[ni][1] = __expf(sc[ni][1] - mn0);
                sc[ni][2] = __expf(sc[ni][2] - mn1);
                sc[ni][3] = __expf(sc[ni][3] - mn1);
                s0 += sc[ni][0] + sc[ni][1];
                s1 += sc[ni][2] + sc[ni][3];
            }
            s0 += __shfl_xor_sync(0xffffffffu, s0, 1);
            s0 += __shfl_xor_sync(0xffffffffu, s0, 2);
            s1 += __shfl_xor_sync(0xffffffffu, s1, 1);
            s1 += __shfl_xor_sync(0xffffffffu, s1, 2);
            float c0 = __expf(m0 - mn0), c1 = __expf(m1 - mn1);
            l0s = l0s * c0 + s0; l1s = l1s * c1 + s1;
            m0 = mn0; m1 = mn1;
#pragma unroll
            for (int ni = 0; ni < 8; ni++) {
                o[ni][0] *= c0; o[ni][1] *= c0;
                o[ni][2] *= c1; o[ni][3] *= c1;
            }

            uint32_t ph[4][4], pl[4][4];
#pragma unroll
            for (int kk = 0; kk < 4; kk++) {
                int n0 = 2 * kk, n1 = 2 * kk + 1;
                cvt_hilo(sc[n0][0], sc[n0][1], ph[kk][0], pl[kk][0]);
                cvt_hilo(sc[n0][2], sc[n0][3], ph[kk][1], pl[kk][1]);
                cvt_hilo(sc[n1][0], sc[n1][1], ph[kk][2], pl[kk][2]);
                cvt_hilo(sc[n1][2], sc[n1][3], ph[kk][3], pl[kk][3]);
            }

            // O += P V, ldmatrix fragments, pass-ordered
#pragma unroll
            for (int kk = 0; kk < 4; kk++) {
                const uint32_t kcb = kk * 8 * 4;
#pragma unroll
                for (int nig = 0; nig < 2; nig++) {
                    uint32_t bh[2][4], bl[2][4];
#pragma unroll
                    for (int j2 = 0; j2 < 2; j2++) {
                        uint32_t ad = vbase + fboff[nig * 2 + j2] * 4 + kcb;
                        ldsm_x4(bh[j2][0], bh[j2][1], bh[j2][2], bh[j2][3], ad);
                        ldsm_x4(bl[j2][0], bl[j2][1], bl[j2][2], bl[j2][3], ad + 64 * FST * 4);
                    }
#pragma unroll
                    for (int j2 = 0; j2 < 2; j2++)
#pragma unroll
                        for (int hf = 0; hf < 2; hf++)
                            mma_bf16(o[nig * 4 + j2 * 2 + hf],
                                     ph[kk][0], ph[kk][1], ph[kk][2], ph[kk][3],
                                     bh[j2][hf * 2], bh[j2][hf * 2 + 1]);
#pragma unroll
                    for (int j2 = 0; j2 < 2; j2++)
#pragma unroll
                        for (int hf = 0; hf < 2; hf++)
                            mma_bf16(o[nig * 4 + j2 * 2 + hf],
                                     ph[kk][0], ph[kk][1], ph[kk][2], ph[kk][3],
                                     bl[j2][hf * 2], bl[j2][hf * 2 + 1]);
#pragma unroll
                    for (int j2 = 0; j2 < 2; j2++)
#pragma unroll
                        for (int hf = 0; hf < 2; hf++)
                            mma_bf16(o[nig * 4 + j2 * 2 + hf],
                                     pl[kk][0], pl[kk][1], pl[kk][2], pl[kk][3],
                                     bh[j2][hf * 2], bh[j2][hf * 2 + 1]);
                }
            }
        }
    }

    float inv0 = 1.0f / l0s, inv1 = 1.0f / l1s;
    size_t r0b = (size_t)(b * S_ + ig0) * 512 + h * 32;
    size_t r1b = (size_t)(b * S_ + ig1) * 512 + h * 32;
#pragma unroll
    for (int ni = 0; ni < 8; ni++) {
        int pr = ni * 4 + tq;
        uint32_t hh, ll;
        cvt_hilo(o[ni][0] * inv0, o[ni][1] * inv0, hh, ll);
        g_aoh[r0b + pr] = hh; g_aol[r0b + pr] = ll;
        cvt_hilo(o[ni][2] * inv1, o[ni][3] * inv1, hh, ll);
        g_aoh[r1b + pr] = hh; g_aol[r1b + pr] = ll;
    }
}

// ---------------------------------------------------------------------------
extern "C" void kernel_launch(void* const* d_in, const int* in_sizes, int n_in,
                              void* d_out, int out_size) {
    const float* x     = (const float*)d_in[0];
    const float* w_qkv = (const float*)d_in[1];
    const float* w_out = (const float*)d_in[2];
    float* out = (float*)d_out;

    cudaFuncSetAttribute(mm_ldsm<0>, cudaFuncAttributeMaxDynamicSharedMemorySize, MM_SMEM_BYTES);
    cudaFuncSetAttribute(mm_ldsm<1>, cudaFuncAttributeMaxDynamicSharedMemorySize, MM_SMEM_BYTES);
    cudaFuncSetAttribute(flash_mma,  cudaFuncAttributeMaxDynamicSharedMemorySize, FLASH_SMEM_BYTES);

    uint32_t *xh, *xl, *wqh, *wql, *woh, *wol, *aoh, *aol;
    cudaGetSymbolAddress((void**)&xh,  g_xh);  cudaGetSymbolAddress((void**)&xl,  g_xl);
    cudaGetSymbolAddress((void**)&wqh, g_wqh); cudaGetSymbolAddress((void**)&wql, g_wql);
    cudaGetSymbolAddress((void**)&woh, g_woh); cudaGetSymbolAddress((void**)&wol, g_wol);
    cudaGetSymbolAddress((void**)&aoh, g_aoh); cudaGetSymbolAddress((void**)&aol, g_aol);

    prep_pack<<<(B_*S_*512 + 255) / 256, 256>>>(x,     xh,  xl,  B_*S_*512);
    prep_pack<<<(3*D_*512  + 255) / 256, 256>>>(w_qkv, wqh, wql, 3*D_*512);
    prep_pack<<<(D_*512    + 255) / 256, 256>>>(w_out, woh, wol, D_*512);

    mm_ldsm<0><<<dim3(24, 64), 256, MM_SMEM_BYTES>>>(xh, xl, wqh, wql, nullptr);
    v_convert<<<dim3(S_/64, H_, B_), 256>>>();
    flash_mma<<<dim3(S_/128, H_, B_), 256, FLASH_SMEM_BYTES>>>();
    mm_ldsm<1><<<dim3(8, 64), 256, MM_SMEM_BYTES>>>(aoh, aol, woh, wol, out);
}

// round 12
// speedup vs baseline: 2.8939x; 1.3634x over previous
#include <cuda_runtime.h>
#include <cuda_fp16.h>
#include <cstdint>
#include <math.h>

#define B_  4
#define S_  2048
#define H_  16
#define DK_ 64
#define D_  1024

// Scratch (device globals — allocation-free rule)
__device__ float    g_v [B_*H_*S_*DK_];          // V fp32 [b,h,s,dk]
__device__ uint32_t g_qh[B_*H_*S_*32];           // fp16x2 pairs, hi only
__device__ uint32_t g_kh[B_*H_*S_*32];           // K hi
__device__ uint32_t g_kl[B_*H_*S_*32];           // K lo
__device__ uint32_t g_vh[B_*H_*DK_*(S_/2)];      // V hi, pairs along s
__device__ uint32_t g_vl[B_*H_*DK_*(S_/2)];      // V lo
__device__ uint32_t g_xh [B_*S_*512];            // x hi only
__device__ uint32_t g_wqh[3*D_*512];             // w_qkv hi
__device__ uint32_t g_wql[3*D_*512];             // w_qkv lo
__device__ uint32_t g_woh[D_*512];               // w_out hi
__device__ uint32_t g_wol[D_*512];               // w_out lo
__device__ uint32_t g_aoh[B_*S_*512];            // attention out, hi only

// ======================= helpers ===========================================
__device__ __forceinline__ void mma_f16(float* c,
                                        uint32_t a0, uint32_t a1, uint32_t a2, uint32_t a3,
                                        uint32_t b0, uint32_t b1) {
    asm volatile(
        "mma.sync.aligned.m16n8k16.row.col.f32.f16.f16.f32 "
        "{%0,%1,%2,%3}, {%4,%5,%6,%7}, {%8,%9}, {%0,%1,%2,%3};"
        : "+f"(c[0]), "+f"(c[1]), "+f"(c[2]), "+f"(c[3])
        : "r"(a0), "r"(a1), "r"(a2), "r"(a3), "r"(b0), "r"(b1));
}

__device__ __forceinline__ uint32_t pack_f16(float x, float y) {
    __half2 h = __floats2half2_rn(x, y);
    return *(uint32_t*)&h;
}
__device__ __forceinline__ void cvt_hilo_f16(float x, float y, uint32_t& hi, uint32_t& lo) {
    __half2 h = __floats2half2_rn(x, y);
    float hx = __half2float(__low2half(h));
    float hy = __half2float(__high2half(h));
    __half2 l = __floats2half2_rn(x - hx, y - hy);
    hi = *(uint32_t*)&h;
    lo = *(uint32_t*)&l;
}

__device__ __forceinline__ uint32_t smem_to_u32(const void* p) {
    uint32_t a;
    asm("{ .reg .u64 t; cvta.to.shared.u64 t, %1; cvt.u32.u64 %0, t; }"
        : "=r"(a) : "l"(p));
    return a;
}
__device__ __forceinline__ void cp_async16(uint32_t dst_smem, const void* src) {
    asm volatile("cp.async.cg.shared.global [%0], [%1], 16;"
                 :: "r"(dst_smem), "l"(src) : "memory");
}
__device__ __forceinline__ void cp_commit() {
    asm volatile("cp.async.commit_group;" ::: "memory");
}
template<int N>
__device__ __forceinline__ void cp_wait() {
    asm volatile("cp.async.wait_group %0;" :: "n"(N) : "memory");
}
__device__ __forceinline__ void ldsm_x4(uint32_t& r0, uint32_t& r1, uint32_t& r2,
                                        uint32_t& r3, uint32_t addr) {
    asm volatile("ldmatrix.sync.aligned.m8n8.x4.shared.b16 {%0,%1,%2,%3}, [%4];"
                 : "=r"(r0), "=r"(r1), "=r"(r2), "=r"(r3) : "r"(addr));
}
// soft cap: 50*tanh(s*0.125/50) = 50 - 100/(exp(s*0.005)+1)
__device__ __forceinline__ float softcap(float s) {
    float e = __expf(s * 0.005f);
    return 50.f - __fdividef(100.f, e + 1.f);
}

// ---------------------------------------------------------------------------
// prep: fp32 -> fp16 pairs. P2: hi+lo (weights), P1: hi only (activations)
// ---------------------------------------------------------------------------
__global__ void prep_pack2(const float* __restrict__ src, uint32_t* __restrict__ dh,
                           uint32_t* __restrict__ dl, int npairs) {
    int i = blockIdx.x * blockDim.x + threadIdx.x;
    if (i >= npairs) return;
    float2 v = ((const float2*)src)[i];
    uint32_t hh, ll;
    cvt_hilo_f16(v.x, v.y, hh, ll);
    dh[i] = hh;
    dl[i] = ll;
}
__global__ void prep_pack1(const float* __restrict__ src, uint32_t* __restrict__ dh,
                           int npairs) {
    int i = blockIdx.x * blockDim.x + threadIdx.x;
    if (i >= npairs) return;
    float2 v = ((const float2*)src)[i];
    dh[i] = pack_f16(v.x, v.y);
}

// ---------------------------------------------------------------------------
// fp16x2 NT GEMM: C = A * (Wh + Wl)^T. A single fp16 (hi), W split hi/lo.
// CTA 128x128, chunk = 16 pairs (K=32). smem per buffer: Ah | Wh | Wl.
// ---------------------------------------------------------------------------
#define PST 20
#define MMBUF (3 * 128 * PST)
#define MM_SMEM_BYTES (2 * MMBUF * 4)      // 61440

template<int MODE>
__global__ void __launch_bounds__(256, 2) mm_ldsm(const uint32_t* __restrict__ Ah_,
                                                  const uint32_t* __restrict__ Wh_,
                                                  const uint32_t* __restrict__ Wl_,
                                                  float* __restrict__ C) {
    extern __shared__ uint32_t smu[];
    const int tid = threadIdx.x;
    const int w = tid >> 5, l = tid & 31;
    const int wm = w & 3, wn = w >> 2;
    const int g = l >> 2, tq = l & 3;
    const int r8 = l & 7, seg = l >> 3;
    const int bm = blockIdx.y, bn = blockIdx.x;
    const uint32_t sb = smem_to_u32(smu);

    const uint32_t* srcs[3] = {
        Ah_ + (size_t)bm * 128 * 512,
        Wh_ + (size_t)bn * 128 * 512,
        Wl_ + (size_t)bn * 128 * 512 };

    const int crow = tid >> 1, cpp = (tid & 1) * 8;

    auto issue = [&](int c, int p) {
        uint32_t dst = sb + (uint32_t)((p * MMBUF + crow * PST + cpp) * 4);
#pragma unroll
        for (int m = 0; m < 3; m++) {
            const uint32_t* s = srcs[m] + (size_t)crow * 512 + c * 16 + cpp;
            cp_async16(dst + m * 128 * PST * 4, s);
            cp_async16(dst + m * 128 * PST * 4 + 16, s + 4);
        }
        cp_commit();
    };

    float acc[2][8][4];
#pragma unroll
    for (int mi = 0; mi < 2; mi++)
#pragma unroll
        for (int ni = 0; ni < 8; ni++)
#pragma unroll
            for (int r = 0; r < 4; r++) acc[mi][ni][r] = 0.f;

    uint32_t aoff[2], boff[4];
#pragma unroll
    for (int mi = 0; mi < 2; mi++)
        aoff[mi] = (uint32_t)((wm * 32 + mi * 16 + r8 + (seg & 1) * 8) * PST + (seg >> 1) * 4);
#pragma unroll
    for (int nj = 0; nj < 4; nj++)
        boff[nj] = (uint32_t)(128 * PST +
                              (wn * 64 + nj * 16 + r8 + (seg >> 1) * 8) * PST + (seg & 1) * 4);

    issue(0, 0);

    for (int c = 0; c < 32; c++) {
        const int p = c & 1;
        cp_wait<0>();
        __syncthreads();
        if (c + 1 < 32) issue(c + 1, p ^ 1);
        const uint32_t base = sb + (uint32_t)(p * MMBUF * 4);

#pragma unroll
        for (int ks = 0; ks < 2; ks++) {
            const uint32_t kcb = ks * 8 * 4;
            uint32_t ah[2][4];
#pragma unroll
            for (int mi = 0; mi < 2; mi++)
                ldsm_x4(ah[mi][0], ah[mi][1], ah[mi][2], ah[mi][3],
                        base + aoff[mi] * 4 + kcb);
#pragma unroll
            for (int njp = 0; njp < 2; njp++) {
                uint32_t bh[2][4], bl[2][4];
#pragma unroll
                for (int j2 = 0; j2 < 2; j2++) {
                    uint32_t bd = base + boff[njp * 2 + j2] * 4 + kcb;
                    ldsm_x4(bh[j2][0], bh[j2][1], bh[j2][2], bh[j2][3], bd);
                    ldsm_x4(bl[j2][0], bl[j2][1], bl[j2][2], bl[j2][3], bd + 128 * PST * 4);
                }
#pragma unroll
                for (int j2 = 0; j2 < 2; j2++)
#pragma unroll
                    for (int hf = 0; hf < 2; hf++)
#pragma unroll
                        for (int mi = 0; mi < 2; mi++)
                            mma_f16(acc[mi][(njp * 2 + j2) * 2 + hf],
                                    ah[mi][0], ah[mi][1], ah[mi][2], ah[mi][3],
                                    bh[j2][hf * 2], bh[j2][hf * 2 + 1]);
#pragma unroll
                for (int j2 = 0; j2 < 2; j2++)
#pragma unroll
                    for (int hf = 0; hf < 2; hf++)
#pragma unroll
                        for (int mi = 0; mi < 2; mi++)
                            mma_f16(acc[mi][(njp * 2 + j2) * 2 + hf],
                                    ah[mi][0], ah[mi][1], ah[mi][2], ah[mi][3],
                                    bl[j2][hf * 2], bl[j2][hf * 2 + 1]);
            }
        }
    }

    const int row0 = wm * 32, col0 = wn * 64;
#pragma unroll
    for (int mi = 0; mi < 2; mi++) {
#pragma unroll
        for (int half = 0; half < 2; half++) {
            int r = bm * 128 + row0 + mi * 16 + g + half * 8;
#pragma unroll
            for (int ni = 0; ni < 8; ni++) {
                int cb = bn * 128 + col0 + ni * 8 + 2 * tq;
                float2 val = make_float2(acc[mi][ni][half * 2 + 0],
                                         acc[mi][ni][half * 2 + 1]);
                if (MODE == 0) {
                    int which = cb >> 10;          // 0:q 1:k 2:v
                    int h  = (cb >> 6) & 15;
                    int d0 = cb & 63;
                    int b  = r >> 11;
                    int s  = r & 2047;
                    if (which == 2) {
                        *(float2*)(g_v + (((size_t)(b * H_ + h) * S_ + s) * DK_ + d0)) = val;
                    } else {
                        int pr = d0 >> 1;
                        float invf = exp2f(-(float)pr * (13.28771237954945f / 32.0f));
                        float ang = (float)s * invf;
                        float sn, cs;
                        sincosf(ang, &sn, &cs);
                        float ev = val.x * cs - val.y * sn;
                        float od = val.x * sn + val.y * cs;
                        size_t idx = ((size_t)(b * H_ + h) * S_ + s) * 32 + pr;
                        if (which == 0) {
                            g_qh[idx] = pack_f16(ev, od);          // Q hi only
                        } else {
                            uint32_t hh, ll;
                            cvt_hilo_f16(ev, od, hh, ll);          // K hi+lo
                            g_kh[idx] = hh; g_kl[idx] = ll;
                        }
                    }
                } else {
                    *(float2*)(C + (size_t)r * D_ + cb) = val;
                }
            }
        }
    }
}

// ---------------------------------------------------------------------------
// V transpose + hi/lo fp16 split: g_v [b,h,s,dk] -> g_vh/g_vl [b,h][dk][s/2]
// ---------------------------------------------------------------------------
__global__ void __launch_bounds__(256) v_convert() {
    __shared__ float ts[64 * 65];
    const int tid = threadIdx.x;
    const int kt = blockIdx.x, h = blockIdx.y, b = blockIdx.z;
    const int bh = b * H_ + h;

    const float* src = g_v + ((size_t)bh * S_ + kt * 64) * DK_;
#pragma unroll
    for (int i = 0; i < 4; i++) {
        int f = tid + i * 256;
        int row = f >> 4, c4 = (f & 15) * 4;
        float4 v = *(const float4*)(src + row * DK_ + c4);
        ts[row * 65 + c4 + 0] = v.x;
        ts[row * 65 + c4 + 1] = v.y;
        ts[row * 65 + c4 + 2] = v.z;
        ts[row * 65 + c4 + 3] = v.w;
    }
    __syncthreads();

    const int w = tid >> 5, p = tid & 31;
#pragma unroll
    for (int i = 0; i < 8; i++) {
        int c = w * 8 + i;
        float x1 = ts[(2 * p) * 65 + c];
        float x2 = ts[(2 * p + 1) * 65 + c];
        uint32_t hh, ll;
        cvt_hilo_f16(x1, x2, hh, ll);
        size_t o = ((size_t)bh * 64 + c) * (S_ / 2) + kt * 32 + p;
        g_vh[o] = hh;
        g_vl[o] = ll;
    }
}

// ---------------------------------------------------------------------------
// Flash attention: BQ=128, fp16x2 (Q/P hi-only, K/V hi+lo), cp.async dbl-buf,
// ldmatrix fragments.
// ---------------------------------------------------------------------------
#define FST 36
#define FQW  (128 * FST)              // Q hi only
#define FKVW (4 * 64 * FST)
#define FLASH_SMEM_BYTES ((FQW + 2 * FKVW) * 4)   // 92160

__global__ void __launch_bounds__(256, 2) flash_mma() {
    extern __shared__ uint32_t su[];
    uint32_t* Qh = su;

    const int tid = threadIdx.x;
    const int w = tid >> 5, l = tid & 31;
    const int g = l >> 2, tq = l & 3;
    const int r8 = l & 7, seg = l >> 3;
    const int q0 = (int)(gridDim.x - 1 - blockIdx.x) * 128;
    const int h = blockIdx.y, b = blockIdx.z;
    const size_t bhp = (size_t)(b * H_ + h) * S_ * 32;
    const size_t bhv = (size_t)(b * H_ + h) * 64;
    const uint32_t sb = smem_to_u32(su);

    const int kvrow = tid >> 2;
    const int kvq   = (tid & 3) * 8;

    auto issue_kv = [&](int kt, int s) {
        uint32_t base = sb + (uint32_t)((FQW + s * FKVW + kvrow * FST + kvq) * 4);
        const uint32_t* k_h = g_kh + bhp + (size_t)(kt * 64 + kvrow) * 32 + kvq;
        const uint32_t* k_l = g_kl + bhp + (size_t)(kt * 64 + kvrow) * 32 + kvq;
        const uint32_t* v_h = g_vh + (bhv + kvrow) * (S_ / 2) + kt * 32 + kvq;
        const uint32_t* v_l = g_vl + (bhv + kvrow) * (S_ / 2) + kt * 32 + kvq;
        cp_async16(base,                      k_h);
        cp_async16(base + 16,                 k_h + 4);
        cp_async16(base + 64*FST*4,           k_l);
        cp_async16(base + 64*FST*4 + 16,      k_l + 4);
        cp_async16(base + 2*64*FST*4,         v_h);
        cp_async16(base + 2*64*FST*4 + 16,    v_h + 4);
        cp_async16(base + 3*64*FST*4,         v_l);
        cp_async16(base + 3*64*FST*4 + 16,    v_l + 4);
        cp_commit();
    };

    issue_kv(0, 0);
    {
        int row = tid >> 1, pb = (tid & 1) * 16;
        const uint32_t* sh = g_qh + bhp + (size_t)(q0 + row) * 32 + pb;
        uint32_t d = sb + (uint32_t)((row * FST + pb) * 4);
#pragma unroll
        for (int j = 0; j < 4; j++)
            cp_async16(d + j * 16, sh + j * 4);
        cp_commit();
    }
    cp_wait<0>();
    __syncthreads();

    uint32_t qh[4][4];
#pragma unroll
    for (int kk = 0; kk < 4; kk++) {
        int ra = (w * 16 + g) * FST + kk * 8 + tq;
        int rb = ra + 8 * FST;
        qh[kk][0] = Qh[ra];     qh[kk][1] = Qh[rb];
        qh[kk][2] = Qh[ra + 4]; qh[kk][3] = Qh[rb + 4];
    }

    uint32_t fboff[4];
#pragma unroll
    for (int nj = 0; nj < 4; nj++)
        fboff[nj] = (uint32_t)((nj * 16 + r8 + (seg >> 1) * 8) * FST + (seg & 1) * 4);

    float m0 = -INFINITY, m1 = -INFINITY, l0s = 0.f, l1s = 0.f;
    float o[8][4];
#pragma unroll
    for (int ni = 0; ni < 8; ni++)
#pragma unroll
        for (int r = 0; r < 4; r++) o[ni][r] = 0.f;

    const int ig0 = q0 + w * 16 + g;
    const int ig1 = ig0 + 8;
    const int rowmax = q0 + w * 16 + 15;
    const int nkt = (q0 + 127) >> 6;

    for (int kt = 0; kt <= nkt; kt++) {
        const int p = kt & 1;
        if (kt > 0) cp_wait<0>();
        __syncthreads();
        if (kt < nkt) issue_kv(kt + 1, p ^ 1);

        if (kt * 64 <= rowmax) {
            const uint32_t kbase = sb + (uint32_t)((FQW + p * FKVW) * 4);
            const uint32_t vbase = kbase + 2 * 64 * FST * 4;

            // S = Q K^T (2-pass fp16)
            float sc[8][4];
#pragma unroll
            for (int ni = 0; ni < 8; ni++)
#pragma unroll
                for (int r = 0; r < 4; r++) sc[ni][r] = 0.f;
#pragma unroll
            for (int kk = 0; kk < 4; kk++) {
                const uint32_t kcb = kk * 8 * 4;
#pragma unroll
                for (int nig = 0; nig < 2; nig++) {
                    uint32_t bh[2][4], bl[2][4];
#pragma unroll
                    for (int j2 = 0; j2 < 2; j2++) {
                        uint32_t ad = kbase + fboff[nig * 2 + j2] * 4 + kcb;
                        ldsm_x4(bh[j2][0], bh[j2][1], bh[j2][2], bh[j2][3], ad);
                        ldsm_x4(bl[j2][0], bl[j2][1], bl[j2][2], bl[j2][3], ad + 64 * FST * 4);
                    }
#pragma unroll
                    for (int j2 = 0; j2 < 2; j2++)
#pragma unroll
                        for (int hf = 0; hf < 2; hf++)
                            mma_f16(sc[nig * 4 + j2 * 2 + hf],
                                    qh[kk][0], qh[kk][1], qh[kk][2], qh[kk][3],
                                    bh[j2][hf * 2], bh[j2][hf * 2 + 1]);
#pragma unroll
                    for (int j2 = 0; j2 < 2; j2++)
#pragma unroll
                        for (int hf = 0; hf < 2; hf++)
                            mma_f16(sc[nig * 4 + j2 * 2 + hf],
                                    qh[kk][0], qh[kk][1], qh[kk][2], qh[kk][3],
                                    bl[j2][hf * 2], bl[j2][hf * 2 + 1]);
                }
            }

            // scale + softcap (fast) + causal mask
            const bool diag = (kt * 64 + 63) > ig0;
#pragma unroll
            for (int ni = 0; ni < 8; ni++) {
                int jg = kt * 64 + ni * 8 + 2 * tq;
#pragma unroll
                for (int r = 0; r < 4; r++) {
                    float v = softcap(sc[ni][r]);
                    if (diag) {
                        int col = jg + (r & 1);
                        int row = (r < 2) ? ig0 : ig1;
                        if (col > row) v = -1e30f;
                    }
                    sc[ni][r] = v;
                }
            }

            // online softmax
            float mx0 = -INFINITY, mx1 = -INFINITY;
#pragma unroll
            for (int ni = 0; ni < 8; ni++) {
                mx0 = fmaxf(mx0, fmaxf(sc[ni][0], sc[ni][1]));
                mx1 = fmaxf(mx1, fmaxf(sc[ni][2], sc[ni][3]));
            }
            mx0 = fmaxf(mx0, __shfl_xor_sync(0xffffffffu, mx0, 1));
            mx0 = fmaxf(mx0, __shfl_xor_sync(0xffffffffu, mx0, 2));
            mx1 = fmaxf(mx1, __shfl_xor_sync(0xffffffffu, mx1, 1));
            mx1 = fmaxf(mx1, __shfl_xor_sync(0xffffffffu, mx1, 2));
            float mn0 = fmaxf(m0, mx0), mn1 = fmaxf(m1, mx1);
            float s0 = 0.f, s1 = 0.f;
#pragma unroll
            for (int ni = 0; ni < 8; ni++) {
                sc[ni][0] = __expf(sc[ni][0] - mn0);
                sc[ni][1] = __expf(sc[ni][1] - mn0);
                sc[ni][2] = __expf(sc[ni][2] - mn1);
                sc[ni][3] = __expf(sc[ni][3] - mn1);
                s0 += sc[ni][0] + sc[ni][1];
                s1 += sc[ni][2] + sc[ni][3];
            }
            s0 += __shfl_xor_sync(0xffffffffu, s0, 1);
            s0 += __shfl_xor_sync(0xffffffffu, s0, 2);
            s1 += __shfl_xor_sync(0xffffffffu, s1, 1);
            s1 += __shfl_xor_sync(0xffffffffu, s1, 2);
            float c0 = __expf(m0 - mn0), c1 = __expf(m1 - mn1);
            l0s = l0s * c0 + s0; l1s = l1s * c1 + s1;
            m0 = mn0; m1 = mn1;
#pragma unroll
            for (int ni = 0; ni < 8; ni++) {
                o[ni][0] *= c0; o[ni][1] *= c0;
                o[ni][2] *= c1; o[ni][3] *= c1;
            }

            // pack P hi-only A-fragments
            uint32_t ph[4][4];
#pragma unroll
            for (int kk = 0; kk < 4; kk++) {
                int n0 = 2 * kk, n1 = 2 * kk + 1;
                ph[kk][0] = pack_f16(sc[n0][0], sc[n0][1]);
                ph[kk][1] = pack_f16(sc[n0][2], sc[n0][3]);
                ph[kk][2] = pack_f16(sc[n1][0], sc[n1][1]);
                ph[kk][3] = pack_f16(sc[n1][2], sc[n1][3]);
            }

            // O += P V (2-pass fp16)
#pragma unroll
            for (int kk = 0; kk < 4; kk++) {
                const uint32_t kcb = kk * 8 * 4;
#pragma unroll
                for (int nig = 0; nig < 2; nig++) {
                    uint32_t bh[2][4], bl[2][4];
#pragma unroll
                    for (int j2 = 0; j2 < 2; j2++) {
                        uint32_t ad = vbase + fboff[nig * 2 + j2] * 4 + kcb;
                        ldsm_x4(bh[j2][0], bh[j2][1], bh[j2][2], bh[j2][3], ad);
                        ldsm_x4(bl[j2][0], bl[j2][1], bl[j2][2], bl[j2][3], ad + 64 * FST * 4);
                    }
#pragma unroll
                    for (int j2 = 0; j2 < 2; j2++)
#pragma unroll
                        for (int hf = 0; hf < 2; hf++)
                            mma_f16(o[nig * 4 + j2 * 2 + hf],
                                    ph[kk][0], ph[kk][1], ph[kk][2], ph[kk][3],
                                    bh[j2][hf * 2], bh[j2][hf * 2 + 1]);
#pragma unroll
                    for (int j2 = 0; j2 < 2; j2++)
#pragma unroll
                        for (int hf = 0; hf < 2; hf++)
                            mma_f16(o[nig * 4 + j2 * 2 + hf],
                                    ph[kk][0], ph[kk][1], ph[kk][2], ph[kk][3],
                                    bl[j2][hf * 2], bl[j2][hf * 2 + 1]);
                }
            }
        }
    }

    // epilogue: normalize, write hi-only packed pairs [b,s][512]
    float inv0 = 1.0f / l0s, inv1 = 1.0f / l1s;
    size_t r0b = (size_t)(b * S_ + ig0) * 512 + h * 32;
    size_t r1b = (size_t)(b * S_ + ig1) * 512 + h * 32;
#pragma unroll
    for (int ni = 0; ni < 8; ni++) {
        int pr = ni * 4 + tq;
        g_aoh[r0b + pr] = pack_f16(o[ni][0] * inv0, o[ni][1] * inv0);
        g_aoh[r1b + pr] = pack_f16(o[ni][2] * inv1, o[ni][3] * inv1);
    }
}

// ---------------------------------------------------------------------------
extern "C" void kernel_launch(void* const* d_in, const int* in_sizes, int n_in,
                              void* d_out, int out_size) {
    const float* x     = (const float*)d_in[0];
    const float* w_qkv = (const float*)d_in[1];
    const float* w_out = (const float*)d_in[2];
    float* out = (float*)d_out;

    cudaFuncSetAttribute(mm_ldsm<0>, cudaFuncAttributeMaxDynamicSharedMemorySize, MM_SMEM_BYTES);
    cudaFuncSetAttribute(mm_ldsm<1>, cudaFuncAttributeMaxDynamicSharedMemorySize, MM_SMEM_BYTES);
    cudaFuncSetAttribute(flash_mma,  cudaFuncAttributeMaxDynamicSharedMemorySize, FLASH_SMEM_BYTES);

    uint32_t *xh, *wqh, *wql, *woh, *wol, *aoh;
    cudaGetSymbolAddress((void**)&xh,  g_xh);
    cudaGetSymbolAddress((void**)&wqh, g_wqh); cudaGetSymbolAddress((void**)&wql, g_wql);
    cudaGetSymbolAddress((void**)&woh, g_woh); cudaGetSymbolAddress((void**)&wol, g_wol);
    cudaGetSymbolAddress((void**)&aoh, g_aoh);

    // 0) pre-pack: activations hi-only, weights hi+lo
    prep_pack1<<<(B_*S_*512 + 255) / 256, 256>>>(x,     xh,  B_*S_*512);
    prep_pack2<<<(3*D_*512  + 255) / 256, 256>>>(w_qkv, wqh, wql, 3*D_*512);
    prep_pack2<<<(D_*512    + 255) / 256, 256>>>(w_out, woh, wol, D_*512);

    // 1) QKV projection + fused RoPE
    mm_ldsm<0><<<dim3(24, 64), 256, MM_SMEM_BYTES>>>(xh, wqh, wql, nullptr);

    // 2) V transpose + hi/lo split
    v_convert<<<dim3(S_/64, H_, B_), 256>>>();

    // 3) Flash attention
    flash_mma<<<dim3(S_/128, H_, B_), 256, FLASH_SMEM_BYTES>>>();

    // 4) Output projection
    mm_ldsm<1><<<dim3(8, 64), 256, MM_SMEM_BYTES>>>(aoh, woh, wol, out);
}